// round 12
// baseline (speedup 1.0000x reference)
#include <cuda_runtime.h>
#include <cuda_fp16.h>
#include <cstdint>

#define BB 2
#define NN 4096
#define DD 512
#define HH 8
#define DHH 64
#define MM (BB*NN)
#define SC2F 0.1803368801111f   // 0.125 * log2(e), folded into Q

// ---------------- scratch (__device__ globals; allocation-free rule) -------
__device__ __align__(256) __half g_xh[MM*DD];          // x in fp16 [m][512]
__device__ __align__(256) __half g_wh[4*DD*DD];        // Wq,Wk,Wv,Wo fp16
__device__ __align__(256) __half g_qh[BB*HH*NN*DHH];   // [bh][n][dh], pre-scaled
__device__ __align__(256) __half g_kh[BB*HH*NN*DHH];
__device__ __align__(256) __half g_vh[BB*HH*NN*DHH];
__device__ __align__(256) __half g_attnh[MM*DD];       // [b][n][(h d)] fp16

#define SWZ(o) ((o) ^ (((o) >> 3) & 0x70))

__device__ __forceinline__ uint32_t smem_u32(const void* p) {
    uint32_t a;
    asm("{ .reg .u64 t; cvta.to.shared.u64 t, %1; cvt.u32.u64 %0, t; }"
        : "=r"(a) : "l"(p));
    return a;
}
__device__ __forceinline__ uint32_t pack_f16x2(float lo, float hi) {
    uint32_t r;
    asm("cvt.rn.f16x2.f32 %0, %1, %2;" : "=r"(r) : "f"(hi), "f"(lo));
    return r;
}
__device__ __forceinline__ uint32_t ex2_f16x2(uint32_t a) {
    uint32_t r;
    asm("ex2.approx.f16x2 %0, %1;" : "=r"(r) : "r"(a));
    return r;
}
__device__ __forceinline__ void hadd2_acc(uint32_t& acc, uint32_t v) {
    asm("add.rn.f16x2 %0, %0, %1;" : "+r"(acc) : "r"(v));
}
__device__ __forceinline__ float hsum2_f32(uint32_t a) {
    float lo, hi;
    asm("{ .reg .f16 h0, h1;\n\t mov.b32 {h0, h1}, %2;\n\t"
        "cvt.f32.f16 %0, h0;\n\t cvt.f32.f16 %1, h1; }"
        : "=f"(lo), "=f"(hi) : "r"(a));
    return lo + hi;
}
__device__ __forceinline__ void ldsm4(uint32_t a, uint32_t& r0, uint32_t& r1,
                                      uint32_t& r2, uint32_t& r3) {
    asm volatile("ldmatrix.sync.aligned.m8n8.x4.shared.b16 {%0,%1,%2,%3}, [%4];"
                 : "=r"(r0), "=r"(r1), "=r"(r2), "=r"(r3) : "r"(a));
}
__device__ __forceinline__ void ldsm4t(uint32_t a, uint32_t& r0, uint32_t& r1,
                                       uint32_t& r2, uint32_t& r3) {
    asm volatile("ldmatrix.sync.aligned.m8n8.x4.trans.shared.b16 {%0,%1,%2,%3}, [%4];"
                 : "=r"(r0), "=r"(r1), "=r"(r2), "=r"(r3) : "r"(a));
}
__device__ __forceinline__ void mma16816(float* c, const uint32_t* a,
                                         uint32_t b0, uint32_t b1) {
    asm volatile(
        "mma.sync.aligned.m16n8k16.row.col.f32.f16.f16.f32 "
        "{%0,%1,%2,%3}, {%4,%5,%6,%7}, {%8,%9}, {%0,%1,%2,%3};"
        : "+f"(c[0]), "+f"(c[1]), "+f"(c[2]), "+f"(c[3])
        : "r"(a[0]), "r"(a[1]), "r"(a[2]), "r"(a[3]), "r"(b0), "r"(b1));
}
__device__ __forceinline__ void cp16(uint32_t dst, const void* src) {
    asm volatile("cp.async.cg.shared.global [%0], [%1], 16;"
                 :: "r"(dst), "l"(src));
}
#define CP_COMMIT() asm volatile("cp.async.commit_group;")
#define CP_WAIT(N)  asm volatile("cp.async.wait_group %0;" :: "n"(N))

__device__ __forceinline__ uint32_t ldsm_addr(uint32_t base, int r0, int c0,
                                              int lane) {
    uint32_t bo = (uint32_t)(r0 + (lane & 15)) * 128u
                + (uint32_t)(c0 + (lane >> 4)) * 16u;
    return base + SWZ(bo);
}

// ---------------------------------------------------------------------------
// fused fp32 -> fp16 converter: blocks [0,4096) convert x, [4096,5120) the Ws
// ---------------------------------------------------------------------------
__global__ __launch_bounds__(256) void cvt_all_kernel(
    const float* __restrict__ x,  const float* __restrict__ Wq,
    const float* __restrict__ Wk, const float* __restrict__ Wv,
    const float* __restrict__ Wo)
{
    if (blockIdx.x < 4096) {
        int i = blockIdx.x * 256 + threadIdx.x;
        float4 v = *(const float4*)(x + (size_t)i * 4);
        uint2 h;
        h.x = pack_f16x2(v.x, v.y);
        h.y = pack_f16x2(v.z, v.w);
        *(uint2*)(g_xh + (size_t)i * 4) = h;
    } else {
        int j = (blockIdx.x - 4096) * 256 + threadIdx.x;   // [0, 262144)
        int w = j >> 16, idx = j & 65535;
        const float* src = (w == 0) ? Wq : (w == 1) ? Wk : (w == 2) ? Wv : Wo;
        float4 v = *(const float4*)(src + (size_t)idx * 4);
        uint2 h;
        h.x = pack_f16x2(v.x, v.y);
        h.y = pack_f16x2(v.z, v.w);
        *(uint2*)(g_wh + (size_t)w * DD * DD + (size_t)idx * 4) = h;
    }
}

// ---------------------------------------------------------------------------
// Shared HMMA GEMM core: 128x128 tile, BK=64, 8 warps.
// ---------------------------------------------------------------------------
__device__ __forceinline__ void gemm_core(
    const __half* A, const __half* Bw, int rowTile, int colTile,
    char* smem, float acc[4][4][4])
{
    const int tid = threadIdx.x, wid = tid >> 5, lane = tid & 31;
    const int warp_m = wid & 1, warp_n = wid >> 1;
    const uint32_t sb = smem_u32(smem);
    const uint32_t sA[2] = { sb, sb + 16384 };
    const uint32_t sB[2] = { sb + 32768, sb + 49152 };

    {
        const char* ag = (const char*)(A + (size_t)rowTile * DD);
        const char* bg = (const char*)(Bw + colTile);
        #pragma unroll
        for (int t = 0; t < 4; t++) {
            int slot = tid + t * 256;
            int ar = slot >> 3, ac = slot & 7;
            cp16(sA[0] + SWZ((uint32_t)(ar * 128 + ac * 16)),
                 ag + (size_t)ar * (DD*2) + ac * 16);
            int br = slot >> 4, bc = slot & 15;
            cp16(sB[0] + (uint32_t)(bc >> 3) * 8192
                       + SWZ((uint32_t)(br * 128 + (bc & 7) * 16)),
                 bg + (size_t)br * (DD*2) + bc * 16);
        }
        CP_COMMIT();
    }

    for (int kt = 0; kt < 8; kt++) {
        const int buf = kt & 1;
        if (kt < 7) {
            const char* ag = (const char*)(A + (size_t)rowTile * DD + (kt+1) * 64);
            const char* bg = (const char*)(Bw + (size_t)(kt+1) * 64 * DD + colTile);
            #pragma unroll
            for (int t = 0; t < 4; t++) {
                int slot = tid + t * 256;
                int ar = slot >> 3, ac = slot & 7;
                cp16(sA[buf^1] + SWZ((uint32_t)(ar * 128 + ac * 16)),
                     ag + (size_t)ar * (DD*2) + ac * 16);
                int br = slot >> 4, bc = slot & 15;
                cp16(sB[buf^1] + (uint32_t)(bc >> 3) * 8192
                               + SWZ((uint32_t)(br * 128 + (bc & 7) * 16)),
                     bg + (size_t)br * (DD*2) + bc * 16);
            }
            CP_COMMIT();
            CP_WAIT(1);
        } else {
            CP_WAIT(0);
        }
        __syncthreads();

        #pragma unroll
        for (int ks = 0; ks < 4; ks++) {
            uint32_t af[4][4];
            #pragma unroll
            for (int mt = 0; mt < 4; mt++)
                ldsm4(ldsm_addr(sA[buf], warp_m * 64 + mt * 16, ks * 2, lane),
                      af[mt][0], af[mt][1], af[mt][2], af[mt][3]);
            #pragma unroll
            for (int np = 0; np < 2; np++) {
                uint32_t b0, b1, b2, b3;
                int c0 = (warp_n & 1) * 4 + np * 2;
                ldsm4t(ldsm_addr(sB[buf] + (uint32_t)(warp_n >> 1) * 8192,
                                 ks * 16, c0, lane), b0, b1, b2, b3);
                #pragma unroll
                for (int mt = 0; mt < 4; mt++) {
                    mma16816(acc[mt][2*np],   af[mt], b0, b1);
                    mma16816(acc[mt][2*np+1], af[mt], b2, b3);
                }
            }
        }
        __syncthreads();
    }
}

// qkv: C tiles scattered as fp16 into [bh][n][dh]; Q pre-scaled by SC2F
__global__ __launch_bounds__(256) void qkv_hmma_kernel()
{
    extern __shared__ char smem[];
    const __half* Bw = g_wh + (size_t)blockIdx.z * DD * DD;
    __half* out = (blockIdx.z == 0) ? g_qh : (blockIdx.z == 1) ? g_kh : g_vh;
    const float osc = (blockIdx.z == 0) ? SC2F : 1.0f;
    const int rowTile = blockIdx.x * 128, colTile = blockIdx.y * 128;
    float acc[4][4][4] = {};
    gemm_core(g_xh, Bw, rowTile, colTile, smem, acc);

    const int tid = threadIdx.x, wid = tid >> 5, lane = tid & 31;
    const int warp_m = wid & 1, warp_n = wid >> 1;
    #pragma unroll
    for (int mt = 0; mt < 4; mt++) {
        #pragma unroll
        for (int nt = 0; nt < 4; nt++) {
            int row = rowTile + warp_m * 64 + mt * 16 + (lane >> 2);
            int col = colTile + warp_n * 32 + nt * 8 + (lane & 3) * 2;
            int b = row >> 12, n = row & (NN - 1);
            int h = col >> 6, dh = col & 63;
            size_t base = ((size_t)(b * HH + h) * NN) * DHH + (size_t)dh;
            *(uint32_t*)(out + base + (size_t)n * DHH) =
                pack_f16x2(acc[mt][nt][0] * osc, acc[mt][nt][1] * osc);
            *(uint32_t*)(out + base + (size_t)(n + 8) * DHH) =
                pack_f16x2(acc[mt][nt][2] * osc, acc[mt][nt][3] * osc);
        }
    }
}

// proj: C = attn @ Wo + bo, fp32 out
__global__ __launch_bounds__(256) void proj_hmma_kernel(
    const float* __restrict__ bo, float* __restrict__ out)
{
    extern __shared__ char smem[];
    const __half* Bw = g_wh + (size_t)3 * DD * DD;
    const int rowTile = blockIdx.x * 128, colTile = blockIdx.y * 128;
    float acc[4][4][4] = {};
    gemm_core(g_attnh, Bw, rowTile, colTile, smem, acc);

    const int tid = threadIdx.x, wid = tid >> 5, lane = tid & 31;
    const int warp_m = wid & 1, warp_n = wid >> 1;
    #pragma unroll
    for (int nt = 0; nt < 4; nt++) {
        int col = colTile + warp_n * 32 + nt * 8 + (lane & 3) * 2;
        float b0 = bo[col], b1 = bo[col + 1];
        #pragma unroll
        for (int mt = 0; mt < 4; mt++) {
            int row = rowTile + warp_m * 64 + mt * 16 + (lane >> 2);
            *(float2*)(out + (size_t)row * DD + col) =
                make_float2(acc[mt][nt][0] + b0, acc[mt][nt][1] + b1);
            *(float2*)(out + (size_t)(row + 8) * DD + col) =
                make_float2(acc[mt][nt][2] + b0, acc[mt][nt][3] + b1);
        }
    }
}

// ---------------------------------------------------------------------------
// Flash attention (HMMA fp16), FA2 layout Br=128 / 4 warps / 32 rows per warp,
// keys processed in 16-wide QUARTERS (s regs 16 instead of 32), and the Q
// staging buffer ALIASED onto pipeline stage 1 (dead after qf fragment load).
// smem 32KB, regs capped at 128 -> 4 CTAs / 16 warps per SM with the
// 128 B/HMMA crossbar intensity of R10/R11.
// ---------------------------------------------------------------------------
__global__ __launch_bounds__(128, 4) void attn_mma_kernel()
{
    __shared__ __align__(1024) char smem_raw[32768];

    const int tid = threadIdx.x, wid = tid >> 5, lane = tid & 31;
    const int bh = blockIdx.y, qblk = blockIdx.x;
    const char* qg  = (const char*)(g_qh + (size_t)bh * NN * DHH + (size_t)qblk * 128 * DHH);
    const char* kg0 = (const char*)(g_kh + (size_t)bh * NN * DHH);
    const char* vg0 = (const char*)(g_vh + (size_t)bh * NN * DHH);

    const uint32_t sb = smem_u32(smem_raw);
    const uint32_t sKb[2] = { sb, sb + 16384 };          // K stages @ 0, 16384
    const uint32_t sVb[2] = { sb + 8192, sb + 24576 };   // V stages @ 8192, 24576
    const uint32_t sQ = sb + 16384;                      // Q aliases stage 1

    // hoisted per-lane swizzled inner offsets (identical for Q, K, V)
    uint32_t inner[4];
    #pragma unroll
    for (int j = 0; j < 4; j++)
        inner[j] = SWZ((uint32_t)(lane & 15) * 128u
                       + (uint32_t)(j * 2 + (lane >> 4)) * 16u);

    // cp.async dst offsets for an 8KB tile: 128 threads x 4 chunks
    uint32_t cpdst[4];
    #pragma unroll
    for (int t = 0; t < 4; t++)
        cpdst[t] = SWZ((uint32_t)(tid + t * 128) * 16u);

    // Q (16KB) into the stage-1 region (plain stores) + K/V tile 0 via cp.async
    #pragma unroll
    for (int t = 0; t < 8; t++) {
        uint32_t bo = (uint32_t)(tid + t * 128) * 16u;
        *(uint4*)(smem_raw + 16384 + SWZ(bo)) = *(const uint4*)(qg + bo);
    }
    #pragma unroll
    for (int t = 0; t < 4; t++) {
        uint32_t bo = (uint32_t)(tid + t * 128) * 16u;
        cp16(sKb[0] + cpdst[t], kg0 + bo);
        cp16(sVb[0] + cpdst[t], vg0 + bo);
    }
    CP_COMMIT();
    __syncthreads();

    // persistent Q fragments: rows wid*32 + mt*16
    uint32_t qf[2][4][4];
    #pragma unroll
    for (int mt = 0; mt < 2; mt++)
        #pragma unroll
        for (int ks = 0; ks < 4; ks++)
            ldsm4(sQ + (uint32_t)wid * 4096u + (uint32_t)mt * 2048u + inner[ks],
                  qf[mt][ks][0], qf[mt][ks][1], qf[mt][ks][2], qf[mt][ks][3]);

    float o[2][8][4] = {};
    float l[2][2] = {};

    for (int kb = 0; kb < 64; kb++) {
        const int buf = kb & 1;

        CP_WAIT(0);
        __syncthreads();
        // All warps have loaded qf (iter 0) / finished reading buf^1 (iter>0),
        // so the stage-1 region (aliased with Q) is dead and refillable.
        if (kb < 63) {
            const char* kt = kg0 + (size_t)(kb + 1) * 8192;
            const char* vt = vg0 + (size_t)(kb + 1) * 8192;
            #pragma unroll
            for (int t = 0; t < 4; t++) {
                uint32_t bo = (uint32_t)(tid + t * 128) * 16u;
                cp16(sKb[buf ^ 1] + cpdst[t], kt + bo);
                cp16(sVb[buf ^ 1] + cpdst[t], vt + bo);
            }
            CP_COMMIT();
        }

        // process 64 keys in four 16-wide quarters
        #pragma unroll
        for (int qt = 0; qt < 4; qt++) {
            const uint32_t kqb = sKb[buf] + (uint32_t)qt * 2048u;
            const uint32_t vqb = sVb[buf] + (uint32_t)qt * 2048u;

            // S = Q K^T for 16 keys
            float s[2][2][4] = {};
            #pragma unroll
            for (int ks = 0; ks < 4; ks++) {
                uint32_t r0, r1, r2, r3;
                ldsm4(kqb + inner[ks], r0, r1, r2, r3);
                #pragma unroll
                for (int mt = 0; mt < 2; mt++) {
                    mma16816(s[mt][0], qf[mt][ks], r0, r2);
                    mma16816(s[mt][1], qf[mt][ks], r1, r3);
                }
            }

            // exp + pack + row sums
            uint32_t ap[2][4];
            #pragma unroll
            for (int mt = 0; mt < 2; mt++) {
                uint32_t hl0 = 0u, hl1 = 0u;
                #pragma unroll
                for (int nt = 0; nt < 2; nt++) {
                    uint32_t ea = ex2_f16x2(pack_f16x2(s[mt][nt][0], s[mt][nt][1]));
                    uint32_t eb = ex2_f16x2(pack_f16x2(s[mt][nt][2], s[mt][nt][3]));
                    hadd2_acc(hl0, ea);
                    hadd2_acc(hl1, eb);
                    ap[mt][nt * 2 + 0] = ea;
                    ap[mt][nt * 2 + 1] = eb;
                }
                l[mt][0] += hsum2_f32(hl0);
                l[mt][1] += hsum2_f32(hl1);
            }

            // O += P V for this quarter (V rows qt*16..qt*16+15)
            #pragma unroll
            for (int nt2 = 0; nt2 < 4; nt2++) {
                uint32_t v0, v1, v2, v3;
                ldsm4t(vqb + inner[nt2], v0, v1, v2, v3);
                #pragma unroll
                for (int mt = 0; mt < 2; mt++) {
                    mma16816(o[mt][2*nt2],   ap[mt], v0, v1);
                    mma16816(o[mt][2*nt2+1], ap[mt], v2, v3);
                }
            }
        }
        // no trailing sync — next iteration's leading sync covers it
    }

    // reduce row sums across the quad (lanes sharing a row)
    #pragma unroll
    for (int mt = 0; mt < 2; mt++) {
        #pragma unroll
        for (int p = 0; p < 2; p++) {
            l[mt][p] += __shfl_xor_sync(0xffffffffu, l[mt][p], 1);
            l[mt][p] += __shfl_xor_sync(0xffffffffu, l[mt][p], 2);
        }
    }

    const int b = bh >> 3, h = bh & 7;
    const int cb = (lane & 3) * 2;
    #pragma unroll
    for (int mt = 0; mt < 2; mt++) {
        const float inv0 = 1.f / l[mt][0], inv1 = 1.f / l[mt][1];
        const int r0g = qblk * 128 + wid * 32 + mt * 16 + (lane >> 2);
        #pragma unroll
        for (int nt = 0; nt < 8; nt++) {
            int col = h * DHH + nt * 8 + cb;
            *(uint32_t*)(g_attnh + (size_t)(b * NN + r0g) * DD + col) =
                pack_f16x2(o[mt][nt][0] * inv0, o[mt][nt][1] * inv0);
            *(uint32_t*)(g_attnh + (size_t)(b * NN + r0g + 8) * DD + col) =
                pack_f16x2(o[mt][nt][2] * inv1, o[mt][nt][3] * inv1);
        }
    }
}

extern "C" void kernel_launch(void* const* d_in, const int* in_sizes, int n_in,
                              void* d_out, int out_size)
{
    const float* x  = (const float*)d_in[0];
    const float* Wq = (const float*)d_in[1];
    const float* Wk = (const float*)d_in[2];
    const float* Wv = (const float*)d_in[3];
    const float* Wo = (const float*)d_in[4];
    const float* bo = (const float*)d_in[5];
    float* out = (float*)d_out;

    cudaFuncSetAttribute(qkv_hmma_kernel,
                         cudaFuncAttributeMaxDynamicSharedMemorySize, 65536);
    cudaFuncSetAttribute(proj_hmma_kernel,
                         cudaFuncAttributeMaxDynamicSharedMemorySize, 65536);

    cvt_all_kernel<<<5120, 256>>>(x, Wq, Wk, Wv, Wo);
    qkv_hmma_kernel<<<dim3(64, 4, 3), 256, 65536>>>();
    attn_mma_kernel<<<dim3(32, 16), 128>>>();
    proj_hmma_kernel<<<dim3(64, 4), 256, 65536>>>(bo, out);
}

// round 13
// speedup vs baseline: 1.1653x; 1.1653x over previous
#include <cuda_runtime.h>
#include <cuda_fp16.h>
#include <cstdint>

#define BB 2
#define NN 4096
#define DD 512
#define HH 8
#define DHH 64
#define MM (BB*NN)
#define SC2F 0.1803368801111f   // 0.125 * log2(e), folded into Q

// ---------------- scratch (__device__ globals; allocation-free rule) -------
__device__ __align__(256) __half g_xh[MM*DD];          // x in fp16 [m][512]
__device__ __align__(256) __half g_wh[4*DD*DD];        // Wq,Wk,Wv,Wo fp16
__device__ __align__(256) __half g_qh[BB*HH*NN*DHH];   // [bh][n][dh], pre-scaled
__device__ __align__(256) __half g_kh[BB*HH*NN*DHH];
__device__ __align__(256) __half g_vh[BB*HH*NN*DHH];
__device__ __align__(256) __half g_attnh[MM*DD];       // [b][n][(h d)] fp16

#define SWZ(o) ((o) ^ (((o) >> 3) & 0x70))

__device__ __forceinline__ uint32_t smem_u32(const void* p) {
    uint32_t a;
    asm("{ .reg .u64 t; cvta.to.shared.u64 t, %1; cvt.u32.u64 %0, t; }"
        : "=r"(a) : "l"(p));
    return a;
}
__device__ __forceinline__ uint32_t pack_f16x2(float lo, float hi) {
    uint32_t r;
    asm("cvt.rn.f16x2.f32 %0, %1, %2;" : "=r"(r) : "f"(hi), "f"(lo));
    return r;
}
__device__ __forceinline__ uint32_t ex2_f16x2(uint32_t a) {
    uint32_t r;
    asm("ex2.approx.f16x2 %0, %1;" : "=r"(r) : "r"(a));
    return r;
}
__device__ __forceinline__ void hadd2_acc(uint32_t& acc, uint32_t v) {
    asm("add.rn.f16x2 %0, %0, %1;" : "+r"(acc) : "r"(v));
}
__device__ __forceinline__ float hsum2_f32(uint32_t a) {
    float lo, hi;
    asm("{ .reg .f16 h0, h1;\n\t mov.b32 {h0, h1}, %2;\n\t"
        "cvt.f32.f16 %0, h0;\n\t cvt.f32.f16 %1, h1; }"
        : "=f"(lo), "=f"(hi) : "r"(a));
    return lo + hi;
}
__device__ __forceinline__ void ldsm4(uint32_t a, uint32_t& r0, uint32_t& r1,
                                      uint32_t& r2, uint32_t& r3) {
    asm volatile("ldmatrix.sync.aligned.m8n8.x4.shared.b16 {%0,%1,%2,%3}, [%4];"
                 : "=r"(r0), "=r"(r1), "=r"(r2), "=r"(r3) : "r"(a));
}
__device__ __forceinline__ void ldsm4t(uint32_t a, uint32_t& r0, uint32_t& r1,
                                       uint32_t& r2, uint32_t& r3) {
    asm volatile("ldmatrix.sync.aligned.m8n8.x4.trans.shared.b16 {%0,%1,%2,%3}, [%4];"
                 : "=r"(r0), "=r"(r1), "=r"(r2), "=r"(r3) : "r"(a));
}
__device__ __forceinline__ void mma16816(float* c, const uint32_t* a,
                                         uint32_t b0, uint32_t b1) {
    asm volatile(
        "mma.sync.aligned.m16n8k16.row.col.f32.f16.f16.f32 "
        "{%0,%1,%2,%3}, {%4,%5,%6,%7}, {%8,%9}, {%0,%1,%2,%3};"
        : "+f"(c[0]), "+f"(c[1]), "+f"(c[2]), "+f"(c[3])
        : "r"(a[0]), "r"(a[1]), "r"(a[2]), "r"(a[3]), "r"(b0), "r"(b1));
}
__device__ __forceinline__ void cp16(uint32_t dst, const void* src) {
    asm volatile("cp.async.cg.shared.global [%0], [%1], 16;"
                 :: "r"(dst), "l"(src));
}
#define CP_COMMIT() asm volatile("cp.async.commit_group;")
#define CP_WAIT(N)  asm volatile("cp.async.wait_group %0;" :: "n"(N))

__device__ __forceinline__ uint32_t ldsm_addr(uint32_t base, int r0, int c0,
                                              int lane) {
    uint32_t bo = (uint32_t)(r0 + (lane & 15)) * 128u
                + (uint32_t)(c0 + (lane >> 4)) * 16u;
    return base + SWZ(bo);
}

// ---------------------------------------------------------------------------
// fused fp32 -> fp16 converter: blocks [0,4096) convert x, [4096,5120) the Ws
// ---------------------------------------------------------------------------
__global__ __launch_bounds__(256) void cvt_all_kernel(
    const float* __restrict__ x,  const float* __restrict__ Wq,
    const float* __restrict__ Wk, const float* __restrict__ Wv,
    const float* __restrict__ Wo)
{
    if (blockIdx.x < 4096) {
        int i = blockIdx.x * 256 + threadIdx.x;
        float4 v = *(const float4*)(x + (size_t)i * 4);
        uint2 h;
        h.x = pack_f16x2(v.x, v.y);
        h.y = pack_f16x2(v.z, v.w);
        *(uint2*)(g_xh + (size_t)i * 4) = h;
    } else {
        int j = (blockIdx.x - 4096) * 256 + threadIdx.x;
        int w = j >> 16, idx = j & 65535;
        const float* src = (w == 0) ? Wq : (w == 1) ? Wk : (w == 2) ? Wv : Wo;
        float4 v = *(const float4*)(src + (size_t)idx * 4);
        uint2 h;
        h.x = pack_f16x2(v.x, v.y);
        h.y = pack_f16x2(v.z, v.w);
        *(uint2*)(g_wh + (size_t)w * DD * DD + (size_t)idx * 4) = h;
    }
}

// ---------------------------------------------------------------------------
// HMMA GEMM core, 3-stage cp.async pipeline (two-tile lookahead):
// C[128x128] = A[128x512] @ B[512x128], 8 warps, one __syncthreads per tile.
// smem: A stages @ 0/16K/32K (16KB each), B stages @ 48K/64K/80K.
// ---------------------------------------------------------------------------
__device__ __forceinline__ void gemm_load_tile(
    uint32_t sA, uint32_t sB, const __half* A, const __half* Bw,
    int rowTile, int colTile, int kt, int tid)
{
    const char* ag = (const char*)(A + (size_t)rowTile * DD + kt * 64);
    const char* bg = (const char*)(Bw + (size_t)kt * 64 * DD + colTile);
    #pragma unroll
    for (int t = 0; t < 4; t++) {
        int slot = tid + t * 256;
        int ar = slot >> 3, ac = slot & 7;
        cp16(sA + SWZ((uint32_t)(ar * 128 + ac * 16)),
             ag + (size_t)ar * (DD*2) + ac * 16);
        int br = slot >> 4, bc = slot & 15;
        cp16(sB + (uint32_t)(bc >> 3) * 8192
                + SWZ((uint32_t)(br * 128 + (bc & 7) * 16)),
             bg + (size_t)br * (DD*2) + bc * 16);
    }
}

__device__ __forceinline__ void gemm_core(
    const __half* A, const __half* Bw, int rowTile, int colTile,
    char* smem, float acc[4][4][4])
{
    const int tid = threadIdx.x, wid = tid >> 5, lane = tid & 31;
    const int warp_m = wid & 1, warp_n = wid >> 1;
    const uint32_t sb = smem_u32(smem);
    const uint32_t sA[3] = { sb, sb + 16384, sb + 32768 };
    const uint32_t sB[3] = { sb + 49152, sb + 65536, sb + 81920 };

    // prologue: tiles 0 and 1 in flight
    gemm_load_tile(sA[0], sB[0], A, Bw, rowTile, colTile, 0, tid);
    CP_COMMIT();
    gemm_load_tile(sA[1], sB[1], A, Bw, rowTile, colTile, 1, tid);
    CP_COMMIT();

    #pragma unroll
    for (int kt = 0; kt < 8; kt++) {
        const int buf = kt % 3;
        if (kt < 7) { CP_WAIT(1); } else { CP_WAIT(0); }
        __syncthreads();
        // stage (kt+2)%3 == (kt-1)%3 is dead (all warps passed the sync)
        if (kt + 2 < 8) {
            gemm_load_tile(sA[(kt + 2) % 3], sB[(kt + 2) % 3],
                           A, Bw, rowTile, colTile, kt + 2, tid);
            CP_COMMIT();
        }

        #pragma unroll
        for (int ks = 0; ks < 4; ks++) {
            uint32_t af[4][4];
            #pragma unroll
            for (int mt = 0; mt < 4; mt++)
                ldsm4(ldsm_addr(sA[buf], warp_m * 64 + mt * 16, ks * 2, lane),
                      af[mt][0], af[mt][1], af[mt][2], af[mt][3]);
            #pragma unroll
            for (int np = 0; np < 2; np++) {
                uint32_t b0, b1, b2, b3;
                int c0 = (warp_n & 1) * 4 + np * 2;
                ldsm4t(ldsm_addr(sB[buf] + (uint32_t)(warp_n >> 1) * 8192,
                                 ks * 16, c0, lane), b0, b1, b2, b3);
                #pragma unroll
                for (int mt = 0; mt < 4; mt++) {
                    mma16816(acc[mt][2*np],   af[mt], b0, b1);
                    mma16816(acc[mt][2*np+1], af[mt], b2, b3);
                }
            }
        }
        // no trailing sync — next iteration's leading sync covers liveness
    }
}

// qkv: C tiles scattered as fp16 into [bh][n][dh]; Q pre-scaled by SC2F
__global__ __launch_bounds__(256) void qkv_hmma_kernel()
{
    extern __shared__ char smem[];
    const __half* Bw = g_wh + (size_t)blockIdx.z * DD * DD;
    __half* out = (blockIdx.z == 0) ? g_qh : (blockIdx.z == 1) ? g_kh : g_vh;
    const float osc = (blockIdx.z == 0) ? SC2F : 1.0f;
    const int rowTile = blockIdx.x * 128, colTile = blockIdx.y * 128;
    float acc[4][4][4] = {};
    gemm_core(g_xh, Bw, rowTile, colTile, smem, acc);

    const int tid = threadIdx.x, wid = tid >> 5, lane = tid & 31;
    const int warp_m = wid & 1, warp_n = wid >> 1;
    #pragma unroll
    for (int mt = 0; mt < 4; mt++) {
        #pragma unroll
        for (int nt = 0; nt < 4; nt++) {
            int row = rowTile + warp_m * 64 + mt * 16 + (lane >> 2);
            int col = colTile + warp_n * 32 + nt * 8 + (lane & 3) * 2;
            int b = row >> 12, n = row & (NN - 1);
            int h = col >> 6, dh = col & 63;
            size_t base = ((size_t)(b * HH + h) * NN) * DHH + (size_t)dh;
            *(uint32_t*)(out + base + (size_t)n * DHH) =
                pack_f16x2(acc[mt][nt][0] * osc, acc[mt][nt][1] * osc);
            *(uint32_t*)(out + base + (size_t)(n + 8) * DHH) =
                pack_f16x2(acc[mt][nt][2] * osc, acc[mt][nt][3] * osc);
        }
    }
}

// proj: C = attn @ Wo + bo, fp32 out
__global__ __launch_bounds__(256) void proj_hmma_kernel(
    const float* __restrict__ bo, float* __restrict__ out)
{
    extern __shared__ char smem[];
    const __half* Bw = g_wh + (size_t)3 * DD * DD;
    const int rowTile = blockIdx.x * 128, colTile = blockIdx.y * 128;
    float acc[4][4][4] = {};
    gemm_core(g_attnh, Bw, rowTile, colTile, smem, acc);

    const int tid = threadIdx.x, wid = tid >> 5, lane = tid & 31;
    const int warp_m = wid & 1, warp_n = wid >> 1;
    #pragma unroll
    for (int nt = 0; nt < 4; nt++) {
        int col = colTile + warp_n * 32 + nt * 8 + (lane & 3) * 2;
        float b0 = bo[col], b1 = bo[col + 1];
        #pragma unroll
        for (int mt = 0; mt < 4; mt++) {
            int row = rowTile + warp_m * 64 + mt * 16 + (lane >> 2);
            *(float2*)(out + (size_t)row * DD + col) =
                make_float2(acc[mt][nt][0] + b0, acc[mt][nt][1] + b1);
            *(float2*)(out + (size_t)(row + 8) * DD + col) =
                make_float2(acc[mt][nt][2] + b0, acc[mt][nt][3] + b1);
        }
    }
}

// ---------------------------------------------------------------------------
// Flash attention (HMMA fp16) — EXACT R9 configuration (best measured:
// 221.9us, regs 96): 4 warps x 16 rows, intra-tile exp interleave,
// single __syncthreads per tile, __launch_bounds__(128, 5).
// ---------------------------------------------------------------------------
__global__ __launch_bounds__(128, 5) void attn_mma_kernel()
{
    __shared__ __align__(1024) char sQ[8192];
    __shared__ __align__(1024) char sK[2][8192];
    __shared__ __align__(1024) char sV[2][8192];

    const int tid = threadIdx.x, wid = tid >> 5, lane = tid & 31;
    const int bh = blockIdx.y, qblk = blockIdx.x;
    const char* qg  = (const char*)(g_qh + (size_t)bh * NN * DHH + (size_t)qblk * 64 * DHH);
    const char* kg0 = (const char*)(g_kh + (size_t)bh * NN * DHH);
    const char* vg0 = (const char*)(g_vh + (size_t)bh * NN * DHH);

    const uint32_t sQb = smem_u32(sQ);
    const uint32_t sKb[2] = { smem_u32(sK[0]), smem_u32(sK[1]) };
    const uint32_t sVb[2] = { smem_u32(sV[0]), smem_u32(sV[1]) };

    uint32_t inner[4];
    #pragma unroll
    for (int j = 0; j < 4; j++)
        inner[j] = SWZ((uint32_t)(lane & 15) * 128u
                       + (uint32_t)(j * 2 + (lane >> 4)) * 16u);

    uint32_t cpdst[4];
    #pragma unroll
    for (int t = 0; t < 4; t++)
        cpdst[t] = SWZ((uint32_t)(tid + t * 128) * 16u);

    #pragma unroll
    for (int t = 0; t < 4; t++) {
        uint32_t bo = (uint32_t)(tid + t * 128) * 16u;
        *(uint4*)(sQ + cpdst[t]) = *(const uint4*)(qg + bo);
    }
    #pragma unroll
    for (int t = 0; t < 4; t++) {
        uint32_t bo = (uint32_t)(tid + t * 128) * 16u;
        cp16(sKb[0] + cpdst[t], kg0 + bo);
        cp16(sVb[0] + cpdst[t], vg0 + bo);
    }
    CP_COMMIT();
    __syncthreads();

    uint32_t qf[4][4];
    #pragma unroll
    for (int ks = 0; ks < 4; ks++)
        ldsm4(sQb + (uint32_t)wid * 2048u + inner[ks],
              qf[ks][0], qf[ks][1], qf[ks][2], qf[ks][3]);

    float o[8][4] = {};
    float l0 = 0.f, l1 = 0.f;

    for (int kb = 0; kb < 64; kb++) {
        const int buf = kb & 1;

        CP_WAIT(0);
        __syncthreads();

        if (kb < 63) {
            const char* kt = kg0 + (size_t)(kb + 1) * 8192;
            const char* vt = vg0 + (size_t)(kb + 1) * 8192;
            #pragma unroll
            for (int t = 0; t < 4; t++) {
                uint32_t bo = (uint32_t)(tid + t * 128) * 16u;
                cp16(sKb[buf ^ 1] + cpdst[t], kt + bo);
                cp16(sVb[buf ^ 1] + cpdst[t], vt + bo);
            }
            CP_COMMIT();
        }

        // ---- S = Q K^T, all 16 MMAs ----
        float s[8][4] = {};
        #pragma unroll
        for (int ng = 0; ng < 4; ng++) {
            const uint32_t kbase = sKb[buf] + (uint32_t)ng * 2048u;
            #pragma unroll
            for (int ks = 0; ks < 4; ks++) {
                uint32_t r0, r1, r2, r3;
                ldsm4(kbase + inner[ks], r0, r1, r2, r3);
                mma16816(s[2*ng],   qf[ks], r0, r2);
                mma16816(s[2*ng+1], qf[ks], r1, r3);
            }
        }

        uint32_t ap[4][4];
        // exp first half (overlaps ng=2,3 drain)
        {
            uint32_t hl0 = 0u, hl1 = 0u;
            #pragma unroll
            for (int nt = 0; nt < 4; nt++) {
                uint32_t ea = ex2_f16x2(pack_f16x2(s[nt][0], s[nt][1]));
                uint32_t eb = ex2_f16x2(pack_f16x2(s[nt][2], s[nt][3]));
                hadd2_acc(hl0, ea);
                hadd2_acc(hl1, eb);
                ap[nt >> 1][(nt & 1) * 2 + 0] = ea;
                ap[nt >> 1][(nt & 1) * 2 + 1] = eb;
            }
            l0 += hsum2_f32(hl0);
            l1 += hsum2_f32(hl1);
        }
        // PV ks=0,1
        #pragma unroll
        for (int ks = 0; ks < 2; ks++) {
            const uint32_t vbase = sVb[buf] + (uint32_t)ks * 2048u;
            #pragma unroll
            for (int nt2 = 0; nt2 < 4; nt2++) {
                uint32_t v0, v1, v2, v3;
                ldsm4t(vbase + inner[nt2], v0, v1, v2, v3);
                mma16816(o[2*nt2],   ap[ks], v0, v1);
                mma16816(o[2*nt2+1], ap[ks], v2, v3);
            }
        }
        // exp second half (overlaps PV ks=0,1 drain)
        {
            uint32_t hl0 = 0u, hl1 = 0u;
            #pragma unroll
            for (int nt = 4; nt < 8; nt++) {
                uint32_t ea = ex2_f16x2(pack_f16x2(s[nt][0], s[nt][1]));
                uint32_t eb = ex2_f16x2(pack_f16x2(s[nt][2], s[nt][3]));
                hadd2_acc(hl0, ea);
                hadd2_acc(hl1, eb);
                ap[nt >> 1][(nt & 1) * 2 + 0] = ea;
                ap[nt >> 1][(nt & 1) * 2 + 1] = eb;
            }
            l0 += hsum2_f32(hl0);
            l1 += hsum2_f32(hl1);
        }
        // PV ks=2,3
        #pragma unroll
        for (int ks = 2; ks < 4; ks++) {
            const uint32_t vbase = sVb[buf] + (uint32_t)ks * 2048u;
            #pragma unroll
            for (int nt2 = 0; nt2 < 4; nt2++) {
                uint32_t v0, v1, v2, v3;
                ldsm4t(vbase + inner[nt2], v0, v1, v2, v3);
                mma16816(o[2*nt2],   ap[ks], v0, v1);
                mma16816(o[2*nt2+1], ap[ks], v2, v3);
            }
        }
        // no trailing sync — next iteration's leading sync provides it
    }

    l0 += __shfl_xor_sync(0xffffffffu, l0, 1);
    l0 += __shfl_xor_sync(0xffffffffu, l0, 2);
    l1 += __shfl_xor_sync(0xffffffffu, l1, 1);
    l1 += __shfl_xor_sync(0xffffffffu, l1, 2);
    const float inv0 = 1.f / l0, inv1 = 1.f / l1;

    const int b = bh >> 3, h = bh & 7;
    const int r0g = qblk * 64 + wid * 16 + (lane >> 2);
    const int cb = (lane & 3) * 2;
    #pragma unroll
    for (int nt = 0; nt < 8; nt++) {
        int col = h * DHH + nt * 8 + cb;
        *(uint32_t*)(g_attnh + (size_t)(b * NN + r0g) * DD + col) =
            pack_f16x2(o[nt][0] * inv0, o[nt][1] * inv0);
        *(uint32_t*)(g_attnh + (size_t)(b * NN + r0g + 8) * DD + col) =
            pack_f16x2(o[nt][2] * inv1, o[nt][3] * inv1);
    }
}

extern "C" void kernel_launch(void* const* d_in, const int* in_sizes, int n_in,
                              void* d_out, int out_size)
{
    const float* x  = (const float*)d_in[0];
    const float* Wq = (const float*)d_in[1];
    const float* Wk = (const float*)d_in[2];
    const float* Wv = (const float*)d_in[3];
    const float* Wo = (const float*)d_in[4];
    const float* bo = (const float*)d_in[5];
    float* out = (float*)d_out;

    cudaFuncSetAttribute(qkv_hmma_kernel,
                         cudaFuncAttributeMaxDynamicSharedMemorySize, 98304);
    cudaFuncSetAttribute(proj_hmma_kernel,
                         cudaFuncAttributeMaxDynamicSharedMemorySize, 98304);

    cvt_all_kernel<<<5120, 256>>>(x, Wq, Wk, Wv, Wo);
    qkv_hmma_kernel<<<dim3(64, 4, 3), 256, 98304>>>();
    attn_mma_kernel<<<dim3(64, 16), 128>>>();
    proj_hmma_kernel<<<dim3(64, 4), 256, 98304>>>(bo, out);
}

// round 14
// speedup vs baseline: 1.1824x; 1.0147x over previous
#include <cuda_runtime.h>
#include <cuda_fp16.h>
#include <cstdint>

#define BB 2
#define NN 4096
#define DD 512
#define HH 8
#define DHH 64
#define MM (BB*NN)
#define SC2F 0.1803368801111f   // 0.125 * log2(e), folded into Q

// ---------------- scratch (__device__ globals; allocation-free rule) -------
__device__ __align__(256) __half g_xh[MM*DD];          // x in fp16 [m][512]
__device__ __align__(256) __half g_wh[4*DD*DD];        // Wq,Wk,Wv,Wo fp16
__device__ __align__(256) __half g_qh[BB*HH*NN*DHH];   // [bh][n][dh], pre-scaled
__device__ __align__(256) __half g_kh[BB*HH*NN*DHH];
__device__ __align__(256) __half g_vh[BB*HH*NN*DHH];
__device__ __align__(256) __half g_attnh[MM*DD];       // [b][n][(h d)] fp16

#define SWZ(o) ((o) ^ (((o) >> 3) & 0x70))

__device__ __forceinline__ uint32_t smem_u32(const void* p) {
    uint32_t a;
    asm("{ .reg .u64 t; cvta.to.shared.u64 t, %1; cvt.u32.u64 %0, t; }"
        : "=r"(a) : "l"(p));
    return a;
}
__device__ __forceinline__ uint32_t pack_f16x2(float lo, float hi) {
    uint32_t r;
    asm("cvt.rn.f16x2.f32 %0, %1, %2;" : "=r"(r) : "f"(hi), "f"(lo));
    return r;
}
__device__ __forceinline__ uint32_t ex2_f16x2(uint32_t a) {
    uint32_t r;
    asm("ex2.approx.f16x2 %0, %1;" : "=r"(r) : "r"(a));
    return r;
}
__device__ __forceinline__ void hadd2_acc(uint32_t& acc, uint32_t v) {
    asm("add.rn.f16x2 %0, %0, %1;" : "+r"(acc) : "r"(v));
}
__device__ __forceinline__ float hsum2_f32(uint32_t a) {
    float lo, hi;
    asm("{ .reg .f16 h0, h1;\n\t mov.b32 {h0, h1}, %2;\n\t"
        "cvt.f32.f16 %0, h0;\n\t cvt.f32.f16 %1, h1; }"
        : "=f"(lo), "=f"(hi) : "r"(a));
    return lo + hi;
}
__device__ __forceinline__ void ldsm4(uint32_t a, uint32_t& r0, uint32_t& r1,
                                      uint32_t& r2, uint32_t& r3) {
    asm volatile("ldmatrix.sync.aligned.m8n8.x4.shared.b16 {%0,%1,%2,%3}, [%4];"
                 : "=r"(r0), "=r"(r1), "=r"(r2), "=r"(r3) : "r"(a));
}
__device__ __forceinline__ void ldsm4t(uint32_t a, uint32_t& r0, uint32_t& r1,
                                       uint32_t& r2, uint32_t& r3) {
    asm volatile("ldmatrix.sync.aligned.m8n8.x4.trans.shared.b16 {%0,%1,%2,%3}, [%4];"
                 : "=r"(r0), "=r"(r1), "=r"(r2), "=r"(r3) : "r"(a));
}
__device__ __forceinline__ void mma16816(float* c, const uint32_t* a,
                                         uint32_t b0, uint32_t b1) {
    asm volatile(
        "mma.sync.aligned.m16n8k16.row.col.f32.f16.f16.f32 "
        "{%0,%1,%2,%3}, {%4,%5,%6,%7}, {%8,%9}, {%0,%1,%2,%3};"
        : "+f"(c[0]), "+f"(c[1]), "+f"(c[2]), "+f"(c[3])
        : "r"(a[0]), "r"(a[1]), "r"(a[2]), "r"(a[3]), "r"(b0), "r"(b1));
}
__device__ __forceinline__ void cp16(uint32_t dst, const void* src) {
    asm volatile("cp.async.cg.shared.global [%0], [%1], 16;"
                 :: "r"(dst), "l"(src));
}
#define CP_COMMIT() asm volatile("cp.async.commit_group;")
#define CP_WAIT(N)  asm volatile("cp.async.wait_group %0;" :: "n"(N))

__device__ __forceinline__ uint32_t ldsm_addr(uint32_t base, int r0, int c0,
                                              int lane) {
    uint32_t bo = (uint32_t)(r0 + (lane & 15)) * 128u
                + (uint32_t)(c0 + (lane >> 4)) * 16u;
    return base + SWZ(bo);
}

// ---------------------------------------------------------------------------
// fused fp32 -> fp16 converter: blocks [0,4096) convert x, [4096,5120) the Ws
// ---------------------------------------------------------------------------
__global__ __launch_bounds__(256) void cvt_all_kernel(
    const float* __restrict__ x,  const float* __restrict__ Wq,
    const float* __restrict__ Wk, const float* __restrict__ Wv,
    const float* __restrict__ Wo)
{
    if (blockIdx.x < 4096) {
        int i = blockIdx.x * 256 + threadIdx.x;
        float4 v = *(const float4*)(x + (size_t)i * 4);
        uint2 h;
        h.x = pack_f16x2(v.x, v.y);
        h.y = pack_f16x2(v.z, v.w);
        *(uint2*)(g_xh + (size_t)i * 4) = h;
    } else {
        int j = (blockIdx.x - 4096) * 256 + threadIdx.x;
        int w = j >> 16, idx = j & 65535;
        const float* src = (w == 0) ? Wq : (w == 1) ? Wk : (w == 2) ? Wv : Wo;
        float4 v = *(const float4*)(src + (size_t)idx * 4);
        uint2 h;
        h.x = pack_f16x2(v.x, v.y);
        h.y = pack_f16x2(v.z, v.w);
        *(uint2*)(g_wh + (size_t)w * DD * DD + (size_t)idx * 4) = h;
    }
}

// ---------------------------------------------------------------------------
// HMMA GEMM core, 3-stage cp.async pipeline (two-tile lookahead):
// C[128x128] = A[128x512] @ B[512x128], 8 warps, one __syncthreads per tile.
// smem: A stages @ 0/16K/32K (16KB each), B stages @ 48K/64K/80K.
// ---------------------------------------------------------------------------
__device__ __forceinline__ void gemm_load_tile(
    uint32_t sA, uint32_t sB, const __half* A, const __half* Bw,
    int rowTile, int colTile, int kt, int tid)
{
    const char* ag = (const char*)(A + (size_t)rowTile * DD + kt * 64);
    const char* bg = (const char*)(Bw + (size_t)kt * 64 * DD + colTile);
    #pragma unroll
    for (int t = 0; t < 4; t++) {
        int slot = tid + t * 256;
        int ar = slot >> 3, ac = slot & 7;
        cp16(sA + SWZ((uint32_t)(ar * 128 + ac * 16)),
             ag + (size_t)ar * (DD*2) + ac * 16);
        int br = slot >> 4, bc = slot & 15;
        cp16(sB + (uint32_t)(bc >> 3) * 8192
                + SWZ((uint32_t)(br * 128 + (bc & 7) * 16)),
             bg + (size_t)br * (DD*2) + bc * 16);
    }
}

__device__ __forceinline__ void gemm_core(
    const __half* A, const __half* Bw, int rowTile, int colTile,
    char* smem, float acc[4][4][4])
{
    const int tid = threadIdx.x, wid = tid >> 5, lane = tid & 31;
    const int warp_m = wid & 1, warp_n = wid >> 1;
    const uint32_t sb = smem_u32(smem);
    const uint32_t sA[3] = { sb, sb + 16384, sb + 32768 };
    const uint32_t sB[3] = { sb + 49152, sb + 65536, sb + 81920 };

    // prologue: tiles 0 and 1 in flight
    gemm_load_tile(sA[0], sB[0], A, Bw, rowTile, colTile, 0, tid);
    CP_COMMIT();
    gemm_load_tile(sA[1], sB[1], A, Bw, rowTile, colTile, 1, tid);
    CP_COMMIT();

    #pragma unroll
    for (int kt = 0; kt < 8; kt++) {
        const int buf = kt % 3;
        if (kt < 7) { CP_WAIT(1); } else { CP_WAIT(0); }
        __syncthreads();
        // stage (kt+2)%3 == (kt-1)%3 is dead (all warps passed the sync)
        if (kt + 2 < 8) {
            gemm_load_tile(sA[(kt + 2) % 3], sB[(kt + 2) % 3],
                           A, Bw, rowTile, colTile, kt + 2, tid);
            CP_COMMIT();
        }

        #pragma unroll
        for (int ks = 0; ks < 4; ks++) {
            uint32_t af[4][4];
            #pragma unroll
            for (int mt = 0; mt < 4; mt++)
                ldsm4(ldsm_addr(sA[buf], warp_m * 64 + mt * 16, ks * 2, lane),
                      af[mt][0], af[mt][1], af[mt][2], af[mt][3]);
            #pragma unroll
            for (int np = 0; np < 2; np++) {
                uint32_t b0, b1, b2, b3;
                int c0 = (warp_n & 1) * 4 + np * 2;
                ldsm4t(ldsm_addr(sB[buf] + (uint32_t)(warp_n >> 1) * 8192,
                                 ks * 16, c0, lane), b0, b1, b2, b3);
                #pragma unroll
                for (int mt = 0; mt < 4; mt++) {
                    mma16816(acc[mt][2*np],   af[mt], b0, b1);
                    mma16816(acc[mt][2*np+1], af[mt], b2, b3);
                }
            }
        }
        // no trailing sync — next iteration's leading sync covers liveness
    }
}

// qkv: C tiles scattered as fp16 into [bh][n][dh]; Q pre-scaled by SC2F
__global__ __launch_bounds__(256, 2) void qkv_hmma_kernel()
{
    extern __shared__ char smem[];
    const __half* Bw = g_wh + (size_t)blockIdx.z * DD * DD;
    __half* out = (blockIdx.z == 0) ? g_qh : (blockIdx.z == 1) ? g_kh : g_vh;
    const float osc = (blockIdx.z == 0) ? SC2F : 1.0f;
    const int rowTile = blockIdx.x * 128, colTile = blockIdx.y * 128;
    float acc[4][4][4] = {};
    gemm_core(g_xh, Bw, rowTile, colTile, smem, acc);

    const int tid = threadIdx.x, wid = tid >> 5, lane = tid & 31;
    const int warp_m = wid & 1, warp_n = wid >> 1;
    #pragma unroll
    for (int mt = 0; mt < 4; mt++) {
        #pragma unroll
        for (int nt = 0; nt < 4; nt++) {
            int row = rowTile + warp_m * 64 + mt * 16 + (lane >> 2);
            int col = colTile + warp_n * 32 + nt * 8 + (lane & 3) * 2;
            int b = row >> 12, n = row & (NN - 1);
            int h = col >> 6, dh = col & 63;
            size_t base = ((size_t)(b * HH + h) * NN) * DHH + (size_t)dh;
            *(uint32_t*)(out + base + (size_t)n * DHH) =
                pack_f16x2(acc[mt][nt][0] * osc, acc[mt][nt][1] * osc);
            *(uint32_t*)(out + base + (size_t)(n + 8) * DHH) =
                pack_f16x2(acc[mt][nt][2] * osc, acc[mt][nt][3] * osc);
        }
    }
}

// proj: C = attn @ Wo + bo, fp32 out
__global__ __launch_bounds__(256, 2) void proj_hmma_kernel(
    const float* __restrict__ bo, float* __restrict__ out)
{
    extern __shared__ char smem[];
    const __half* Bw = g_wh + (size_t)3 * DD * DD;
    const int rowTile = blockIdx.x * 128, colTile = blockIdx.y * 128;
    float acc[4][4][4] = {};
    gemm_core(g_attnh, Bw, rowTile, colTile, smem, acc);

    const int tid = threadIdx.x, wid = tid >> 5, lane = tid & 31;
    const int warp_m = wid & 1, warp_n = wid >> 1;
    #pragma unroll
    for (int nt = 0; nt < 4; nt++) {
        int col = colTile + warp_n * 32 + nt * 8 + (lane & 3) * 2;
        float b0 = bo[col], b1 = bo[col + 1];
        #pragma unroll
        for (int mt = 0; mt < 4; mt++) {
            int row = rowTile + warp_m * 64 + mt * 16 + (lane >> 2);
            *(float2*)(out + (size_t)row * DD + col) =
                make_float2(acc[mt][nt][0] + b0, acc[mt][nt][1] + b1);
            *(float2*)(out + (size_t)(row + 8) * DD + col) =
                make_float2(acc[mt][nt][2] + b0, acc[mt][nt][3] + b1);
        }
    }
}

// ---------------------------------------------------------------------------
// Flash attention (HMMA fp16) — EXACT R9 configuration (best measured:
// 221.9us, regs 96): 4 warps x 16 rows, intra-tile exp interleave,
// single __syncthreads per tile, __launch_bounds__(128, 5).
// ---------------------------------------------------------------------------
__global__ __launch_bounds__(128, 5) void attn_mma_kernel()
{
    __shared__ __align__(1024) char sQ[8192];
    __shared__ __align__(1024) char sK[2][8192];
    __shared__ __align__(1024) char sV[2][8192];

    const int tid = threadIdx.x, wid = tid >> 5, lane = tid & 31;
    const int bh = blockIdx.y, qblk = blockIdx.x;
    const char* qg  = (const char*)(g_qh + (size_t)bh * NN * DHH + (size_t)qblk * 64 * DHH);
    const char* kg0 = (const char*)(g_kh + (size_t)bh * NN * DHH);
    const char* vg0 = (const char*)(g_vh + (size_t)bh * NN * DHH);

    const uint32_t sQb = smem_u32(sQ);
    const uint32_t sKb[2] = { smem_u32(sK[0]), smem_u32(sK[1]) };
    const uint32_t sVb[2] = { smem_u32(sV[0]), smem_u32(sV[1]) };

    uint32_t inner[4];
    #pragma unroll
    for (int j = 0; j < 4; j++)
        inner[j] = SWZ((uint32_t)(lane & 15) * 128u
                       + (uint32_t)(j * 2 + (lane >> 4)) * 16u);

    uint32_t cpdst[4];
    #pragma unroll
    for (int t = 0; t < 4; t++)
        cpdst[t] = SWZ((uint32_t)(tid + t * 128) * 16u);

    #pragma unroll
    for (int t = 0; t < 4; t++) {
        uint32_t bo = (uint32_t)(tid + t * 128) * 16u;
        *(uint4*)(sQ + cpdst[t]) = *(const uint4*)(qg + bo);
    }
    #pragma unroll
    for (int t = 0; t < 4; t++) {
        uint32_t bo = (uint32_t)(tid + t * 128) * 16u;
        cp16(sKb[0] + cpdst[t], kg0 + bo);
        cp16(sVb[0] + cpdst[t], vg0 + bo);
    }
    CP_COMMIT();
    __syncthreads();

    uint32_t qf[4][4];
    #pragma unroll
    for (int ks = 0; ks < 4; ks++)
        ldsm4(sQb + (uint32_t)wid * 2048u + inner[ks],
              qf[ks][0], qf[ks][1], qf[ks][2], qf[ks][3]);

    float o[8][4] = {};
    float l0 = 0.f, l1 = 0.f;

    for (int kb = 0; kb < 64; kb++) {
        const int buf = kb & 1;

        CP_WAIT(0);
        __syncthreads();

        if (kb < 63) {
            const char* kt = kg0 + (size_t)(kb + 1) * 8192;
            const char* vt = vg0 + (size_t)(kb + 1) * 8192;
            #pragma unroll
            for (int t = 0; t < 4; t++) {
                uint32_t bo = (uint32_t)(tid + t * 128) * 16u;
                cp16(sKb[buf ^ 1] + cpdst[t], kt + bo);
                cp16(sVb[buf ^ 1] + cpdst[t], vt + bo);
            }
            CP_COMMIT();
        }

        // ---- S = Q K^T, all 16 MMAs ----
        float s[8][4] = {};
        #pragma unroll
        for (int ng = 0; ng < 4; ng++) {
            const uint32_t kbase = sKb[buf] + (uint32_t)ng * 2048u;
            #pragma unroll
            for (int ks = 0; ks < 4; ks++) {
                uint32_t r0, r1, r2, r3;
                ldsm4(kbase + inner[ks], r0, r1, r2, r3);
                mma16816(s[2*ng],   qf[ks], r0, r2);
                mma16816(s[2*ng+1], qf[ks], r1, r3);
            }
        }

        uint32_t ap[4][4];
        // exp first half (overlaps ng=2,3 drain)
        {
            uint32_t hl0 = 0u, hl1 = 0u;
            #pragma unroll
            for (int nt = 0; nt < 4; nt++) {
                uint32_t ea = ex2_f16x2(pack_f16x2(s[nt][0], s[nt][1]));
                uint32_t eb = ex2_f16x2(pack_f16x2(s[nt][2], s[nt][3]));
                hadd2_acc(hl0, ea);
                hadd2_acc(hl1, eb);
                ap[nt >> 1][(nt & 1) * 2 + 0] = ea;
                ap[nt >> 1][(nt & 1) * 2 + 1] = eb;
            }
            l0 += hsum2_f32(hl0);
            l1 += hsum2_f32(hl1);
        }
        // PV ks=0,1
        #pragma unroll
        for (int ks = 0; ks < 2; ks++) {
            const uint32_t vbase = sVb[buf] + (uint32_t)ks * 2048u;
            #pragma unroll
            for (int nt2 = 0; nt2 < 4; nt2++) {
                uint32_t v0, v1, v2, v3;
                ldsm4t(vbase + inner[nt2], v0, v1, v2, v3);
                mma16816(o[2*nt2],   ap[ks], v0, v1);
                mma16816(o[2*nt2+1], ap[ks], v2, v3);
            }
        }
        // exp second half (overlaps PV ks=0,1 drain)
        {
            uint32_t hl0 = 0u, hl1 = 0u;
            #pragma unroll
            for (int nt = 4; nt < 8; nt++) {
                uint32_t ea = ex2_f16x2(pack_f16x2(s[nt][0], s[nt][1]));
                uint32_t eb = ex2_f16x2(pack_f16x2(s[nt][2], s[nt][3]));
                hadd2_acc(hl0, ea);
                hadd2_acc(hl1, eb);
                ap[nt >> 1][(nt & 1) * 2 + 0] = ea;
                ap[nt >> 1][(nt & 1) * 2 + 1] = eb;
            }
            l0 += hsum2_f32(hl0);
            l1 += hsum2_f32(hl1);
        }
        // PV ks=2,3
        #pragma unroll
        for (int ks = 2; ks < 4; ks++) {
            const uint32_t vbase = sVb[buf] + (uint32_t)ks * 2048u;
            #pragma unroll
            for (int nt2 = 0; nt2 < 4; nt2++) {
                uint32_t v0, v1, v2, v3;
                ldsm4t(vbase + inner[nt2], v0, v1, v2, v3);
                mma16816(o[2*nt2],   ap[ks], v0, v1);
                mma16816(o[2*nt2+1], ap[ks], v2, v3);
            }
        }
        // no trailing sync — next iteration's leading sync provides it
    }

    l0 += __shfl_xor_sync(0xffffffffu, l0, 1);
    l0 += __shfl_xor_sync(0xffffffffu, l0, 2);
    l1 += __shfl_xor_sync(0xffffffffu, l1, 1);
    l1 += __shfl_xor_sync(0xffffffffu, l1, 2);
    const float inv0 = 1.f / l0, inv1 = 1.f / l1;

    const int b = bh >> 3, h = bh & 7;
    const int r0g = qblk * 64 + wid * 16 + (lane >> 2);
    const int cb = (lane & 3) * 2;
    #pragma unroll
    for (int nt = 0; nt < 8; nt++) {
        int col = h * DHH + nt * 8 + cb;
        *(uint32_t*)(g_attnh + (size_t)(b * NN + r0g) * DD + col) =
            pack_f16x2(o[nt][0] * inv0, o[nt][1] * inv0);
        *(uint32_t*)(g_attnh + (size_t)(b * NN + r0g + 8) * DD + col) =
            pack_f16x2(o[nt][2] * inv1, o[nt][3] * inv1);
    }
}

extern "C" void kernel_launch(void* const* d_in, const int* in_sizes, int n_in,
                              void* d_out, int out_size)
{
    const float* x  = (const float*)d_in[0];
    const float* Wq = (const float*)d_in[1];
    const float* Wk = (const float*)d_in[2];
    const float* Wv = (const float*)d_in[3];
    const float* Wo = (const float*)d_in[4];
    const float* bo = (const float*)d_in[5];
    float* out = (float*)d_out;

    cudaFuncSetAttribute(qkv_hmma_kernel,
                         cudaFuncAttributeMaxDynamicSharedMemorySize, 98304);
    cudaFuncSetAttribute(proj_hmma_kernel,
                         cudaFuncAttributeMaxDynamicSharedMemorySize, 98304);

    cvt_all_kernel<<<5120, 256>>>(x, Wq, Wk, Wv, Wo);
    qkv_hmma_kernel<<<dim3(64, 4, 3), 256, 98304>>>();
    attn_mma_kernel<<<dim3(64, 16), 128>>>();
    proj_hmma_kernel<<<dim3(64, 4), 256, 98304>>>(bo, out);
}

// round 15
// speedup vs baseline: 1.2581x; 1.0640x over previous
#include <cuda_runtime.h>
#include <cuda_fp16.h>
#include <cstdint>

#define BB 2
#define NN 4096
#define DD 512
#define HH 8
#define DHH 64
#define MM (BB*NN)
#define SC2F 0.1803368801111f   // 0.125 * log2(e), folded into Q

// ---------------- scratch (__device__ globals; allocation-free rule) -------
__device__ __align__(256) __half g_xh[MM*DD];          // x in fp16 [m][512]
__device__ __align__(256) __half g_wh[4*DD*DD];        // Wq,Wk,Wv,Wo fp16
__device__ __align__(256) __half g_qh[BB*HH*NN*DHH];   // [bh][n][dh], pre-scaled
__device__ __align__(256) __half g_kh[BB*HH*NN*DHH];
__device__ __align__(256) __half g_vh[BB*HH*NN*DHH];
__device__ __align__(256) __half g_attnh[MM*DD];       // [b][n][(h d)] fp16

#define SWZ(o) ((o) ^ (((o) >> 3) & 0x70))

__device__ __forceinline__ uint32_t smem_u32(const void* p) {
    uint32_t a;
    asm("{ .reg .u64 t; cvta.to.shared.u64 t, %1; cvt.u32.u64 %0, t; }"
        : "=r"(a) : "l"(p));
    return a;
}
__device__ __forceinline__ uint32_t pack_f16x2(float lo, float hi) {
    uint32_t r;
    asm("cvt.rn.f16x2.f32 %0, %1, %2;" : "=r"(r) : "f"(hi), "f"(lo));
    return r;
}
__device__ __forceinline__ uint32_t ex2_f16x2(uint32_t a) {
    uint32_t r;
    asm("ex2.approx.f16x2 %0, %1;" : "=r"(r) : "r"(a));
    return r;
}
__device__ __forceinline__ void hadd2_acc(uint32_t& acc, uint32_t v) {
    asm("add.rn.f16x2 %0, %0, %1;" : "+r"(acc) : "r"(v));
}
__device__ __forceinline__ float hsum2_f32(uint32_t a) {
    float lo, hi;
    asm("{ .reg .f16 h0, h1;\n\t mov.b32 {h0, h1}, %2;\n\t"
        "cvt.f32.f16 %0, h0;\n\t cvt.f32.f16 %1, h1; }"
        : "=f"(lo), "=f"(hi) : "r"(a));
    return lo + hi;
}
__device__ __forceinline__ void ldsm4(uint32_t a, uint32_t& r0, uint32_t& r1,
                                      uint32_t& r2, uint32_t& r3) {
    asm volatile("ldmatrix.sync.aligned.m8n8.x4.shared.b16 {%0,%1,%2,%3}, [%4];"
                 : "=r"(r0), "=r"(r1), "=r"(r2), "=r"(r3) : "r"(a));
}
__device__ __forceinline__ void ldsm4t(uint32_t a, uint32_t& r0, uint32_t& r1,
                                       uint32_t& r2, uint32_t& r3) {
    asm volatile("ldmatrix.sync.aligned.m8n8.x4.trans.shared.b16 {%0,%1,%2,%3}, [%4];"
                 : "=r"(r0), "=r"(r1), "=r"(r2), "=r"(r3) : "r"(a));
}
__device__ __forceinline__ void mma16816(float* c, const uint32_t* a,
                                         uint32_t b0, uint32_t b1) {
    asm volatile(
        "mma.sync.aligned.m16n8k16.row.col.f32.f16.f16.f32 "
        "{%0,%1,%2,%3}, {%4,%5,%6,%7}, {%8,%9}, {%0,%1,%2,%3};"
        : "+f"(c[0]), "+f"(c[1]), "+f"(c[2]), "+f"(c[3])
        : "r"(a[0]), "r"(a[1]), "r"(a[2]), "r"(a[3]), "r"(b0), "r"(b1));
}
__device__ __forceinline__ void cp16(uint32_t dst, const void* src) {
    asm volatile("cp.async.cg.shared.global [%0], [%1], 16;"
                 :: "r"(dst), "l"(src));
}
#define CP_COMMIT() asm volatile("cp.async.commit_group;")
#define CP_WAIT(N)  asm volatile("cp.async.wait_group %0;" :: "n"(N))

__device__ __forceinline__ uint32_t ldsm_addr(uint32_t base, int r0, int c0,
                                              int lane) {
    uint32_t bo = (uint32_t)(r0 + (lane & 15)) * 128u
                + (uint32_t)(c0 + (lane >> 4)) * 16u;
    return base + SWZ(bo);
}

// ---------------------------------------------------------------------------
// fused fp32 -> fp16 converter: blocks [0,4096) convert x, [4096,5120) the Ws
// ---------------------------------------------------------------------------
__global__ __launch_bounds__(256) void cvt_all_kernel(
    const float* __restrict__ x,  const float* __restrict__ Wq,
    const float* __restrict__ Wk, const float* __restrict__ Wv,
    const float* __restrict__ Wo)
{
    if (blockIdx.x < 4096) {
        int i = blockIdx.x * 256 + threadIdx.x;
        float4 v = *(const float4*)(x + (size_t)i * 4);
        uint2 h;
        h.x = pack_f16x2(v.x, v.y);
        h.y = pack_f16x2(v.z, v.w);
        *(uint2*)(g_xh + (size_t)i * 4) = h;
    } else {
        int j = (blockIdx.x - 4096) * 256 + threadIdx.x;
        int w = j >> 16, idx = j & 65535;
        const float* src = (w == 0) ? Wq : (w == 1) ? Wk : (w == 2) ? Wv : Wo;
        float4 v = *(const float4*)(src + (size_t)idx * 4);
        uint2 h;
        h.x = pack_f16x2(v.x, v.y);
        h.y = pack_f16x2(v.z, v.w);
        *(uint2*)(g_wh + (size_t)w * DD * DD + (size_t)idx * 4) = h;
    }
}

// ---------------------------------------------------------------------------
// HMMA GEMM core, 3-stage cp.async pipeline (two-tile lookahead):
// C[128x128] = A[128x512] @ B[512x128], 8 warps, one __syncthreads per tile.
// smem: A stages @ 0/16K/32K (16KB each), B stages @ 48K/64K/80K.
// ---------------------------------------------------------------------------
__device__ __forceinline__ void gemm_load_tile(
    uint32_t sA, uint32_t sB, const __half* A, const __half* Bw,
    int rowTile, int colTile, int kt, int tid)
{
    const char* ag = (const char*)(A + (size_t)rowTile * DD + kt * 64);
    const char* bg = (const char*)(Bw + (size_t)kt * 64 * DD + colTile);
    #pragma unroll
    for (int t = 0; t < 4; t++) {
        int slot = tid + t * 256;
        int ar = slot >> 3, ac = slot & 7;
        cp16(sA + SWZ((uint32_t)(ar * 128 + ac * 16)),
             ag + (size_t)ar * (DD*2) + ac * 16);
        int br = slot >> 4, bc = slot & 15;
        cp16(sB + (uint32_t)(bc >> 3) * 8192
                + SWZ((uint32_t)(br * 128 + (bc & 7) * 16)),
             bg + (size_t)br * (DD*2) + bc * 16);
    }
}

__device__ __forceinline__ void gemm_core(
    const __half* A, const __half* Bw, int rowTile, int colTile,
    char* smem, float acc[4][4][4])
{
    const int tid = threadIdx.x, wid = tid >> 5, lane = tid & 31;
    const int warp_m = wid & 1, warp_n = wid >> 1;
    const uint32_t sb = smem_u32(smem);
    const uint32_t sA[3] = { sb, sb + 16384, sb + 32768 };
    const uint32_t sB[3] = { sb + 49152, sb + 65536, sb + 81920 };

    gemm_load_tile(sA[0], sB[0], A, Bw, rowTile, colTile, 0, tid);
    CP_COMMIT();
    gemm_load_tile(sA[1], sB[1], A, Bw, rowTile, colTile, 1, tid);
    CP_COMMIT();

    #pragma unroll
    for (int kt = 0; kt < 8; kt++) {
        const int buf = kt % 3;
        if (kt < 7) { CP_WAIT(1); } else { CP_WAIT(0); }
        __syncthreads();
        if (kt + 2 < 8) {
            gemm_load_tile(sA[(kt + 2) % 3], sB[(kt + 2) % 3],
                           A, Bw, rowTile, colTile, kt + 2, tid);
            CP_COMMIT();
        }

        #pragma unroll
        for (int ks = 0; ks < 4; ks++) {
            uint32_t af[4][4];
            #pragma unroll
            for (int mt = 0; mt < 4; mt++)
                ldsm4(ldsm_addr(sA[buf], warp_m * 64 + mt * 16, ks * 2, lane),
                      af[mt][0], af[mt][1], af[mt][2], af[mt][3]);
            #pragma unroll
            for (int np = 0; np < 2; np++) {
                uint32_t b0, b1, b2, b3;
                int c0 = (warp_n & 1) * 4 + np * 2;
                ldsm4t(ldsm_addr(sB[buf] + (uint32_t)(warp_n >> 1) * 8192,
                                 ks * 16, c0, lane), b0, b1, b2, b3);
                #pragma unroll
                for (int mt = 0; mt < 4; mt++) {
                    mma16816(acc[mt][2*np],   af[mt], b0, b1);
                    mma16816(acc[mt][2*np+1], af[mt], b2, b3);
                }
            }
        }
    }
}

// qkv: C tiles scattered as fp16 into [bh][n][dh]; Q pre-scaled by SC2F
__global__ __launch_bounds__(256, 2) void qkv_hmma_kernel()
{
    extern __shared__ char smem[];
    const __half* Bw = g_wh + (size_t)blockIdx.z * DD * DD;
    __half* out = (blockIdx.z == 0) ? g_qh : (blockIdx.z == 1) ? g_kh : g_vh;
    const float osc = (blockIdx.z == 0) ? SC2F : 1.0f;
    const int rowTile = blockIdx.x * 128, colTile = blockIdx.y * 128;
    float acc[4][4][4] = {};
    gemm_core(g_xh, Bw, rowTile, colTile, smem, acc);

    const int tid = threadIdx.x, wid = tid >> 5, lane = tid & 31;
    const int warp_m = wid & 1, warp_n = wid >> 1;
    #pragma unroll
    for (int mt = 0; mt < 4; mt++) {
        #pragma unroll
        for (int nt = 0; nt < 4; nt++) {
            int row = rowTile + warp_m * 64 + mt * 16 + (lane >> 2);
            int col = colTile + warp_n * 32 + nt * 8 + (lane & 3) * 2;
            int b = row >> 12, n = row & (NN - 1);
            int h = col >> 6, dh = col & 63;
            size_t base = ((size_t)(b * HH + h) * NN) * DHH + (size_t)dh;
            *(uint32_t*)(out + base + (size_t)n * DHH) =
                pack_f16x2(acc[mt][nt][0] * osc, acc[mt][nt][1] * osc);
            *(uint32_t*)(out + base + (size_t)(n + 8) * DHH) =
                pack_f16x2(acc[mt][nt][2] * osc, acc[mt][nt][3] * osc);
        }
    }
}

// proj: C = attn @ Wo + bo, fp32 out
__global__ __launch_bounds__(256, 2) void proj_hmma_kernel(
    const float* __restrict__ bo, float* __restrict__ out)
{
    extern __shared__ char smem[];
    const __half* Bw = g_wh + (size_t)3 * DD * DD;
    const int rowTile = blockIdx.x * 128, colTile = blockIdx.y * 128;
    float acc[4][4][4] = {};
    gemm_core(g_attnh, Bw, rowTile, colTile, smem, acc);

    const int tid = threadIdx.x, wid = tid >> 5, lane = tid & 31;
    const int warp_m = wid & 1, warp_n = wid >> 1;
    #pragma unroll
    for (int nt = 0; nt < 4; nt++) {
        int col = colTile + warp_n * 32 + nt * 8 + (lane & 3) * 2;
        float b0 = bo[col], b1 = bo[col + 1];
        #pragma unroll
        for (int mt = 0; mt < 4; mt++) {
            int row = rowTile + warp_m * 64 + mt * 16 + (lane >> 2);
            *(float2*)(out + (size_t)row * DD + col) =
                make_float2(acc[mt][nt][0] + b0, acc[mt][nt][1] + b1);
            *(float2*)(out + (size_t)(row + 8) * DD + col) =
                make_float2(acc[mt][nt][2] + b0, acc[mt][nt][3] + b1);
        }
    }
}

// ---------------------------------------------------------------------------
// Flash attention (HMMA fp16) — R9 config + DEFERRED PV ks=3:
// at tile end, load V-fragments for ks=3 and snapshot ap[3], but issue those
// 16 MMAs right AFTER the next tile's __syncthreads (operands all in regs,
// zero dependencies) -> fills the barrier/prefetch tensor bubble.
// Peak regs ~110 (vdef overlaps dead s); __launch_bounds__(128, 4).
// ---------------------------------------------------------------------------
__global__ __launch_bounds__(128, 4) void attn_mma_kernel()
{
    __shared__ __align__(1024) char sQ[8192];
    __shared__ __align__(1024) char sK[2][8192];
    __shared__ __align__(1024) char sV[2][8192];

    const int tid = threadIdx.x, wid = tid >> 5, lane = tid & 31;
    const int bh = blockIdx.y, qblk = blockIdx.x;
    const char* qg  = (const char*)(g_qh + (size_t)bh * NN * DHH + (size_t)qblk * 64 * DHH);
    const char* kg0 = (const char*)(g_kh + (size_t)bh * NN * DHH);
    const char* vg0 = (const char*)(g_vh + (size_t)bh * NN * DHH);

    const uint32_t sQb = smem_u32(sQ);
    const uint32_t sKb[2] = { smem_u32(sK[0]), smem_u32(sK[1]) };
    const uint32_t sVb[2] = { smem_u32(sV[0]), smem_u32(sV[1]) };

    uint32_t inner[4];
    #pragma unroll
    for (int j = 0; j < 4; j++)
        inner[j] = SWZ((uint32_t)(lane & 15) * 128u
                       + (uint32_t)(j * 2 + (lane >> 4)) * 16u);

    uint32_t cpdst[4];
    #pragma unroll
    for (int t = 0; t < 4; t++)
        cpdst[t] = SWZ((uint32_t)(tid + t * 128) * 16u);

    #pragma unroll
    for (int t = 0; t < 4; t++) {
        uint32_t bo = (uint32_t)(tid + t * 128) * 16u;
        *(uint4*)(sQ + cpdst[t]) = *(const uint4*)(qg + bo);
    }
    #pragma unroll
    for (int t = 0; t < 4; t++) {
        uint32_t bo = (uint32_t)(tid + t * 128) * 16u;
        cp16(sKb[0] + cpdst[t], kg0 + bo);
        cp16(sVb[0] + cpdst[t], vg0 + bo);
    }
    CP_COMMIT();
    __syncthreads();

    uint32_t qf[4][4];
    #pragma unroll
    for (int ks = 0; ks < 4; ks++)
        ldsm4(sQb + (uint32_t)wid * 2048u + inner[ks],
              qf[ks][0], qf[ks][1], qf[ks][2], qf[ks][3]);

    float o[8][4] = {};
    float l0 = 0.f, l1 = 0.f;
    uint32_t vdef[16];   // deferred ks=3 V fragments
    uint32_t ap3[4];     // deferred ks=3 P fragments

    for (int kb = 0; kb < 64; kb++) {
        const int buf = kb & 1;

        CP_WAIT(0);
        __syncthreads();

        // ---- deferred PV ks=3 of the previous tile: reg-only, no deps ----
        if (kb > 0) {
            #pragma unroll
            for (int nt2 = 0; nt2 < 4; nt2++) {
                mma16816(o[2*nt2],   ap3, vdef[4*nt2+0], vdef[4*nt2+1]);
                mma16816(o[2*nt2+1], ap3, vdef[4*nt2+2], vdef[4*nt2+3]);
            }
        }

        if (kb < 63) {
            const char* kt = kg0 + (size_t)(kb + 1) * 8192;
            const char* vt = vg0 + (size_t)(kb + 1) * 8192;
            #pragma unroll
            for (int t = 0; t < 4; t++) {
                uint32_t bo = (uint32_t)(tid + t * 128) * 16u;
                cp16(sKb[buf ^ 1] + cpdst[t], kt + bo);
                cp16(sVb[buf ^ 1] + cpdst[t], vt + bo);
            }
            CP_COMMIT();
        }

        // ---- S = Q K^T, all 16 MMAs ----
        float s[8][4] = {};
        #pragma unroll
        for (int ng = 0; ng < 4; ng++) {
            const uint32_t kbase = sKb[buf] + (uint32_t)ng * 2048u;
            #pragma unroll
            for (int ks = 0; ks < 4; ks++) {
                uint32_t r0, r1, r2, r3;
                ldsm4(kbase + inner[ks], r0, r1, r2, r3);
                mma16816(s[2*ng],   qf[ks], r0, r2);
                mma16816(s[2*ng+1], qf[ks], r1, r3);
            }
        }

        uint32_t ap[4][4];
        // exp first half (overlaps ng=2,3 drain)
        {
            uint32_t hl0 = 0u, hl1 = 0u;
            #pragma unroll
            for (int nt = 0; nt < 4; nt++) {
                uint32_t ea = ex2_f16x2(pack_f16x2(s[nt][0], s[nt][1]));
                uint32_t eb = ex2_f16x2(pack_f16x2(s[nt][2], s[nt][3]));
                hadd2_acc(hl0, ea);
                hadd2_acc(hl1, eb);
                ap[nt >> 1][(nt & 1) * 2 + 0] = ea;
                ap[nt >> 1][(nt & 1) * 2 + 1] = eb;
            }
            l0 += hsum2_f32(hl0);
            l1 += hsum2_f32(hl1);
        }
        // PV ks=0,1
        #pragma unroll
        for (int ks = 0; ks < 2; ks++) {
            const uint32_t vbase = sVb[buf] + (uint32_t)ks * 2048u;
            #pragma unroll
            for (int nt2 = 0; nt2 < 4; nt2++) {
                uint32_t v0, v1, v2, v3;
                ldsm4t(vbase + inner[nt2], v0, v1, v2, v3);
                mma16816(o[2*nt2],   ap[ks], v0, v1);
                mma16816(o[2*nt2+1], ap[ks], v2, v3);
            }
        }
        // exp second half (overlaps PV ks=0,1 drain)
        {
            uint32_t hl0 = 0u, hl1 = 0u;
            #pragma unroll
            for (int nt = 4; nt < 8; nt++) {
                uint32_t ea = ex2_f16x2(pack_f16x2(s[nt][0], s[nt][1]));
                uint32_t eb = ex2_f16x2(pack_f16x2(s[nt][2], s[nt][3]));
                hadd2_acc(hl0, ea);
                hadd2_acc(hl1, eb);
                ap[nt >> 1][(nt & 1) * 2 + 0] = ea;
                ap[nt >> 1][(nt & 1) * 2 + 1] = eb;
            }
            l0 += hsum2_f32(hl0);
            l1 += hsum2_f32(hl1);
        }
        // PV ks=2 (issued now)
        {
            const uint32_t vbase = sVb[buf] + (uint32_t)2 * 2048u;
            #pragma unroll
            for (int nt2 = 0; nt2 < 4; nt2++) {
                uint32_t v0, v1, v2, v3;
                ldsm4t(vbase + inner[nt2], v0, v1, v2, v3);
                mma16816(o[2*nt2],   ap[2], v0, v1);
                mma16816(o[2*nt2+1], ap[2], v2, v3);
            }
        }
        // PV ks=3: load fragments + snapshot ap[3]; MMAs deferred to next tile
        {
            const uint32_t vbase = sVb[buf] + (uint32_t)3 * 2048u;
            #pragma unroll
            for (int nt2 = 0; nt2 < 4; nt2++)
                ldsm4t(vbase + inner[nt2], vdef[4*nt2+0], vdef[4*nt2+1],
                       vdef[4*nt2+2], vdef[4*nt2+3]);
            ap3[0] = ap[3][0]; ap3[1] = ap[3][1];
            ap3[2] = ap[3][2]; ap3[3] = ap[3][3];
        }
        // no trailing sync — next iteration's leading sync provides it
    }

    // flush deferred PV ks=3 of tile 63
    #pragma unroll
    for (int nt2 = 0; nt2 < 4; nt2++) {
        mma16816(o[2*nt2],   ap3, vdef[4*nt2+0], vdef[4*nt2+1]);
        mma16816(o[2*nt2+1], ap3, vdef[4*nt2+2], vdef[4*nt2+3]);
    }

    l0 += __shfl_xor_sync(0xffffffffu, l0, 1);
    l0 += __shfl_xor_sync(0xffffffffu, l0, 2);
    l1 += __shfl_xor_sync(0xffffffffu, l1, 1);
    l1 += __shfl_xor_sync(0xffffffffu, l1, 2);
    const float inv0 = 1.f / l0, inv1 = 1.f / l1;

    const int b = bh >> 3, h = bh & 7;
    const int r0g = qblk * 64 + wid * 16 + (lane >> 2);
    const int cb = (lane & 3) * 2;
    #pragma unroll
    for (int nt = 0; nt < 8; nt++) {
        int col = h * DHH + nt * 8 + cb;
        *(uint32_t*)(g_attnh + (size_t)(b * NN + r0g) * DD + col) =
            pack_f16x2(o[nt][0] * inv0, o[nt][1] * inv0);
        *(uint32_t*)(g_attnh + (size_t)(b * NN + r0g + 8) * DD + col) =
            pack_f16x2(o[nt][2] * inv1, o[nt][3] * inv1);
    }
}

extern "C" void kernel_launch(void* const* d_in, const int* in_sizes, int n_in,
                              void* d_out, int out_size)
{
    const float* x  = (const float*)d_in[0];
    const float* Wq = (const float*)d_in[1];
    const float* Wk = (const float*)d_in[2];
    const float* Wv = (const float*)d_in[3];
    const float* Wo = (const float*)d_in[4];
    const float* bo = (const float*)d_in[5];
    float* out = (float*)d_out;

    cudaFuncSetAttribute(qkv_hmma_kernel,
                         cudaFuncAttributeMaxDynamicSharedMemorySize, 98304);
    cudaFuncSetAttribute(proj_hmma_kernel,
                         cudaFuncAttributeMaxDynamicSharedMemorySize, 98304);

    cvt_all_kernel<<<5120, 256>>>(x, Wq, Wk, Wv, Wo);
    qkv_hmma_kernel<<<dim3(64, 4, 3), 256, 98304>>>();
    attn_mma_kernel<<<dim3(64, 16), 128>>>();
    proj_hmma_kernel<<<dim3(64, 4), 256, 98304>>>(bo, out);
}

// round 16
// speedup vs baseline: 1.2670x; 1.0071x over previous
#include <cuda_runtime.h>
#include <cuda_fp16.h>
#include <cstdint>

#define BB 2
#define NN 4096
#define DD 512
#define HH 8
#define DHH 64
#define MM (BB*NN)
#define SC2F 0.1803368801111f   // 0.125 * log2(e), folded into Q

// ---------------- scratch (__device__ globals; allocation-free rule) -------
__device__ __align__(256) __half g_xh[MM*DD];          // x in fp16 [m][512]
__device__ __align__(256) __half g_wh[4*DD*DD];        // Wq,Wk,Wv,Wo fp16
__device__ __align__(256) __half g_qh[BB*HH*NN*DHH];   // [bh][n][dh], pre-scaled
__device__ __align__(256) __half g_kh[BB*HH*NN*DHH];
__device__ __align__(256) __half g_vh[BB*HH*NN*DHH];
__device__ __align__(256) __half g_attnh[MM*DD];       // [b][n][(h d)] fp16

#define SWZ(o) ((o) ^ (((o) >> 3) & 0x70))

__device__ __forceinline__ uint32_t smem_u32(const void* p) {
    uint32_t a;
    asm("{ .reg .u64 t; cvta.to.shared.u64 t, %1; cvt.u32.u64 %0, t; }"
        : "=r"(a) : "l"(p));
    return a;
}
__device__ __forceinline__ uint32_t pack_f16x2(float lo, float hi) {
    uint32_t r;
    asm("cvt.rn.f16x2.f32 %0, %1, %2;" : "=r"(r) : "f"(hi), "f"(lo));
    return r;
}
__device__ __forceinline__ uint32_t ex2_f16x2(uint32_t a) {
    uint32_t r;
    asm("ex2.approx.f16x2 %0, %1;" : "=r"(r) : "r"(a));
    return r;
}
__device__ __forceinline__ void hadd2_acc(uint32_t& acc, uint32_t v) {
    asm("add.rn.f16x2 %0, %0, %1;" : "+r"(acc) : "r"(v));
}
__device__ __forceinline__ float hsum2_f32(uint32_t a) {
    float lo, hi;
    asm("{ .reg .f16 h0, h1;\n\t mov.b32 {h0, h1}, %2;\n\t"
        "cvt.f32.f16 %0, h0;\n\t cvt.f32.f16 %1, h1; }"
        : "=f"(lo), "=f"(hi) : "r"(a));
    return lo + hi;
}
__device__ __forceinline__ void ldsm4(uint32_t a, uint32_t& r0, uint32_t& r1,
                                      uint32_t& r2, uint32_t& r3) {
    asm volatile("ldmatrix.sync.aligned.m8n8.x4.shared.b16 {%0,%1,%2,%3}, [%4];"
                 : "=r"(r0), "=r"(r1), "=r"(r2), "=r"(r3) : "r"(a));
}
__device__ __forceinline__ void ldsm4t(uint32_t a, uint32_t& r0, uint32_t& r1,
                                       uint32_t& r2, uint32_t& r3) {
    asm volatile("ldmatrix.sync.aligned.m8n8.x4.trans.shared.b16 {%0,%1,%2,%3}, [%4];"
                 : "=r"(r0), "=r"(r1), "=r"(r2), "=r"(r3) : "r"(a));
}
__device__ __forceinline__ void mma16816(float* c, const uint32_t* a,
                                         uint32_t b0, uint32_t b1) {
    asm volatile(
        "mma.sync.aligned.m16n8k16.row.col.f32.f16.f16.f32 "
        "{%0,%1,%2,%3}, {%4,%5,%6,%7}, {%8,%9}, {%0,%1,%2,%3};"
        : "+f"(c[0]), "+f"(c[1]), "+f"(c[2]), "+f"(c[3])
        : "r"(a[0]), "r"(a[1]), "r"(a[2]), "r"(a[3]), "r"(b0), "r"(b1));
}
__device__ __forceinline__ void cp16(uint32_t dst, const void* src) {
    asm volatile("cp.async.cg.shared.global [%0], [%1], 16;"
                 :: "r"(dst), "l"(src));
}
#define CP_COMMIT() asm volatile("cp.async.commit_group;")
#define CP_WAIT(N)  asm volatile("cp.async.wait_group %0;" :: "n"(N))

__device__ __forceinline__ uint32_t ldsm_addr(uint32_t base, int r0, int c0,
                                              int lane) {
    uint32_t bo = (uint32_t)(r0 + (lane & 15)) * 128u
                + (uint32_t)(c0 + (lane >> 4)) * 16u;
    return base + SWZ(bo);
}

// ---------------------------------------------------------------------------
// fused fp32 -> fp16 converter: blocks [0,4096) convert x, [4096,5120) the Ws
// ---------------------------------------------------------------------------
__global__ __launch_bounds__(256) void cvt_all_kernel(
    const float* __restrict__ x,  const float* __restrict__ Wq,
    const float* __restrict__ Wk, const float* __restrict__ Wv,
    const float* __restrict__ Wo)
{
    if (blockIdx.x < 4096) {
        int i = blockIdx.x * 256 + threadIdx.x;
        float4 v = *(const float4*)(x + (size_t)i * 4);
        uint2 h;
        h.x = pack_f16x2(v.x, v.y);
        h.y = pack_f16x2(v.z, v.w);
        *(uint2*)(g_xh + (size_t)i * 4) = h;
    } else {
        int j = (blockIdx.x - 4096) * 256 + threadIdx.x;
        int w = j >> 16, idx = j & 65535;
        const float* src = (w == 0) ? Wq : (w == 1) ? Wk : (w == 2) ? Wv : Wo;
        float4 v = *(const float4*)(src + (size_t)idx * 4);
        uint2 h;
        h.x = pack_f16x2(v.x, v.y);
        h.y = pack_f16x2(v.z, v.w);
        *(uint2*)(g_wh + (size_t)w * DD * DD + (size_t)idx * 4) = h;
    }
}

// ---------------------------------------------------------------------------
// HMMA GEMM core, 3-stage cp.async pipeline (two-tile lookahead):
// C[128x128] = A[128x512] @ B[512x128], 8 warps, one __syncthreads per tile.
// smem: A stages @ 0/16K/32K (16KB each), B stages @ 48K/64K/80K.
// ---------------------------------------------------------------------------
__device__ __forceinline__ void gemm_load_tile(
    uint32_t sA, uint32_t sB, const __half* A, const __half* Bw,
    int rowTile, int colTile, int kt, int tid)
{
    const char* ag = (const char*)(A + (size_t)rowTile * DD + kt * 64);
    const char* bg = (const char*)(Bw + (size_t)kt * 64 * DD + colTile);
    #pragma unroll
    for (int t = 0; t < 4; t++) {
        int slot = tid + t * 256;
        int ar = slot >> 3, ac = slot & 7;
        cp16(sA + SWZ((uint32_t)(ar * 128 + ac * 16)),
             ag + (size_t)ar * (DD*2) + ac * 16);
        int br = slot >> 4, bc = slot & 15;
        cp16(sB + (uint32_t)(bc >> 3) * 8192
                + SWZ((uint32_t)(br * 128 + (bc & 7) * 16)),
             bg + (size_t)br * (DD*2) + bc * 16);
    }
}

__device__ __forceinline__ void gemm_core(
    const __half* A, const __half* Bw, int rowTile, int colTile,
    char* smem, float acc[4][4][4])
{
    const int tid = threadIdx.x, wid = tid >> 5, lane = tid & 31;
    const int warp_m = wid & 1, warp_n = wid >> 1;
    const uint32_t sb = smem_u32(smem);
    const uint32_t sA[3] = { sb, sb + 16384, sb + 32768 };
    const uint32_t sB[3] = { sb + 49152, sb + 65536, sb + 81920 };

    gemm_load_tile(sA[0], sB[0], A, Bw, rowTile, colTile, 0, tid);
    CP_COMMIT();
    gemm_load_tile(sA[1], sB[1], A, Bw, rowTile, colTile, 1, tid);
    CP_COMMIT();

    #pragma unroll
    for (int kt = 0; kt < 8; kt++) {
        const int buf = kt % 3;
        if (kt < 7) { CP_WAIT(1); } else { CP_WAIT(0); }
        __syncthreads();
        if (kt + 2 < 8) {
            gemm_load_tile(sA[(kt + 2) % 3], sB[(kt + 2) % 3],
                           A, Bw, rowTile, colTile, kt + 2, tid);
            CP_COMMIT();
        }

        #pragma unroll
        for (int ks = 0; ks < 4; ks++) {
            uint32_t af[4][4];
            #pragma unroll
            for (int mt = 0; mt < 4; mt++)
                ldsm4(ldsm_addr(sA[buf], warp_m * 64 + mt * 16, ks * 2, lane),
                      af[mt][0], af[mt][1], af[mt][2], af[mt][3]);
            #pragma unroll
            for (int np = 0; np < 2; np++) {
                uint32_t b0, b1, b2, b3;
                int c0 = (warp_n & 1) * 4 + np * 2;
                ldsm4t(ldsm_addr(sB[buf] + (uint32_t)(warp_n >> 1) * 8192,
                                 ks * 16, c0, lane), b0, b1, b2, b3);
                #pragma unroll
                for (int mt = 0; mt < 4; mt++) {
                    mma16816(acc[mt][2*np],   af[mt], b0, b1);
                    mma16816(acc[mt][2*np+1], af[mt], b2, b3);
                }
            }
        }
    }
}

// qkv: C tiles scattered as fp16 into [bh][n][dh]; Q pre-scaled by SC2F
__global__ __launch_bounds__(256, 2) void qkv_hmma_kernel()
{
    extern __shared__ char smem[];
    const __half* Bw = g_wh + (size_t)blockIdx.z * DD * DD;
    __half* out = (blockIdx.z == 0) ? g_qh : (blockIdx.z == 1) ? g_kh : g_vh;
    const float osc = (blockIdx.z == 0) ? SC2F : 1.0f;
    const int rowTile = blockIdx.x * 128, colTile = blockIdx.y * 128;
    float acc[4][4][4] = {};
    gemm_core(g_xh, Bw, rowTile, colTile, smem, acc);

    const int tid = threadIdx.x, wid = tid >> 5, lane = tid & 31;
    const int warp_m = wid & 1, warp_n = wid >> 1;
    #pragma unroll
    for (int mt = 0; mt < 4; mt++) {
        #pragma unroll
        for (int nt = 0; nt < 4; nt++) {
            int row = rowTile + warp_m * 64 + mt * 16 + (lane >> 2);
            int col = colTile + warp_n * 32 + nt * 8 + (lane & 3) * 2;
            int b = row >> 12, n = row & (NN - 1);
            int h = col >> 6, dh = col & 63;
            size_t base = ((size_t)(b * HH + h) * NN) * DHH + (size_t)dh;
            *(uint32_t*)(out + base + (size_t)n * DHH) =
                pack_f16x2(acc[mt][nt][0] * osc, acc[mt][nt][1] * osc);
            *(uint32_t*)(out + base + (size_t)(n + 8) * DHH) =
                pack_f16x2(acc[mt][nt][2] * osc, acc[mt][nt][3] * osc);
        }
    }
}

// proj: C = attn @ Wo + bo, fp32 out
__global__ __launch_bounds__(256, 2) void proj_hmma_kernel(
    const float* __restrict__ bo, float* __restrict__ out)
{
    extern __shared__ char smem[];
    const __half* Bw = g_wh + (size_t)3 * DD * DD;
    const int rowTile = blockIdx.x * 128, colTile = blockIdx.y * 128;
    float acc[4][4][4] = {};
    gemm_core(g_attnh, Bw, rowTile, colTile, smem, acc);

    const int tid = threadIdx.x, wid = tid >> 5, lane = tid & 31;
    const int warp_m = wid & 1, warp_n = wid >> 1;
    #pragma unroll
    for (int nt = 0; nt < 4; nt++) {
        int col = colTile + warp_n * 32 + nt * 8 + (lane & 3) * 2;
        float b0 = bo[col], b1 = bo[col + 1];
        #pragma unroll
        for (int mt = 0; mt < 4; mt++) {
            int row = rowTile + warp_m * 64 + mt * 16 + (lane >> 2);
            *(float2*)(out + (size_t)row * DD + col) =
                make_float2(acc[mt][nt][0] + b0, acc[mt][nt][1] + b1);
            *(float2*)(out + (size_t)(row + 8) * DD + col) =
                make_float2(acc[mt][nt][2] + b0, acc[mt][nt][3] + b1);
        }
    }
}

// ---------------------------------------------------------------------------
// Flash attention (HMMA fp16) — R9 config + DEFERRED PV ks=2 AND ks=3:
// at tile end, load V-fragments for ks=2,3 into vdef[32]; the 32 MMAs are
// issued right AFTER the next tile's __syncthreads, reading ap[2]/ap[3]
// directly (ap is loop-persistent; the deferred block runs before exp
// rewrites it). vdef never co-lives with s (s dead at tile tail, reborn
// after vdef dies) -> peak regs ~130 at the (128, 4) cap.
// ---------------------------------------------------------------------------
__global__ __launch_bounds__(128, 4) void attn_mma_kernel()
{
    __shared__ __align__(1024) char sQ[8192];
    __shared__ __align__(1024) char sK[2][8192];
    __shared__ __align__(1024) char sV[2][8192];

    const int tid = threadIdx.x, wid = tid >> 5, lane = tid & 31;
    const int bh = blockIdx.y, qblk = blockIdx.x;
    const char* qg  = (const char*)(g_qh + (size_t)bh * NN * DHH + (size_t)qblk * 64 * DHH);
    const char* kg0 = (const char*)(g_kh + (size_t)bh * NN * DHH);
    const char* vg0 = (const char*)(g_vh + (size_t)bh * NN * DHH);

    const uint32_t sQb = smem_u32(sQ);
    const uint32_t sKb[2] = { smem_u32(sK[0]), smem_u32(sK[1]) };
    const uint32_t sVb[2] = { smem_u32(sV[0]), smem_u32(sV[1]) };

    uint32_t inner[4];
    #pragma unroll
    for (int j = 0; j < 4; j++)
        inner[j] = SWZ((uint32_t)(lane & 15) * 128u
                       + (uint32_t)(j * 2 + (lane >> 4)) * 16u);

    uint32_t cpdst[4];
    #pragma unroll
    for (int t = 0; t < 4; t++)
        cpdst[t] = SWZ((uint32_t)(tid + t * 128) * 16u);

    #pragma unroll
    for (int t = 0; t < 4; t++) {
        uint32_t bo = (uint32_t)(tid + t * 128) * 16u;
        *(uint4*)(sQ + cpdst[t]) = *(const uint4*)(qg + bo);
    }
    #pragma unroll
    for (int t = 0; t < 4; t++) {
        uint32_t bo = (uint32_t)(tid + t * 128) * 16u;
        cp16(sKb[0] + cpdst[t], kg0 + bo);
        cp16(sVb[0] + cpdst[t], vg0 + bo);
    }
    CP_COMMIT();
    __syncthreads();

    uint32_t qf[4][4];
    #pragma unroll
    for (int ks = 0; ks < 4; ks++)
        ldsm4(sQb + (uint32_t)wid * 2048u + inner[ks],
              qf[ks][0], qf[ks][1], qf[ks][2], qf[ks][3]);

    float o[8][4] = {};
    float l0 = 0.f, l1 = 0.f;
    uint32_t vdef[32];   // deferred ks=2 (0..15) and ks=3 (16..31) V fragments
    uint32_t ap[4][4];   // loop-persistent P fragments

    for (int kb = 0; kb < 64; kb++) {
        const int buf = kb & 1;

        CP_WAIT(0);
        __syncthreads();

        // ---- deferred PV ks=2,3 of the previous tile: reg-only, no deps ----
        // (ap[2], ap[3] still hold the previous tile's values; exp below
        //  rewrites them only after this block.)
        if (kb > 0) {
            #pragma unroll
            for (int nt2 = 0; nt2 < 4; nt2++) {
                mma16816(o[2*nt2],   ap[2], vdef[4*nt2+0], vdef[4*nt2+1]);
                mma16816(o[2*nt2+1], ap[2], vdef[4*nt2+2], vdef[4*nt2+3]);
            }
            #pragma unroll
            for (int nt2 = 0; nt2 < 4; nt2++) {
                mma16816(o[2*nt2],   ap[3], vdef[16+4*nt2+0], vdef[16+4*nt2+1]);
                mma16816(o[2*nt2+1], ap[3], vdef[16+4*nt2+2], vdef[16+4*nt2+3]);
            }
        }

        if (kb < 63) {
            const char* kt = kg0 + (size_t)(kb + 1) * 8192;
            const char* vt = vg0 + (size_t)(kb + 1) * 8192;
            #pragma unroll
            for (int t = 0; t < 4; t++) {
                uint32_t bo = (uint32_t)(tid + t * 128) * 16u;
                cp16(sKb[buf ^ 1] + cpdst[t], kt + bo);
                cp16(sVb[buf ^ 1] + cpdst[t], vt + bo);
            }
            CP_COMMIT();
        }

        // ---- S = Q K^T, all 16 MMAs ----
        float s[8][4] = {};
        #pragma unroll
        for (int ng = 0; ng < 4; ng++) {
            const uint32_t kbase = sKb[buf] + (uint32_t)ng * 2048u;
            #pragma unroll
            for (int ks = 0; ks < 4; ks++) {
                uint32_t r0, r1, r2, r3;
                ldsm4(kbase + inner[ks], r0, r1, r2, r3);
                mma16816(s[2*ng],   qf[ks], r0, r2);
                mma16816(s[2*ng+1], qf[ks], r1, r3);
            }
        }

        // exp first half (overlaps ng=2,3 drain)
        {
            uint32_t hl0 = 0u, hl1 = 0u;
            #pragma unroll
            for (int nt = 0; nt < 4; nt++) {
                uint32_t ea = ex2_f16x2(pack_f16x2(s[nt][0], s[nt][1]));
                uint32_t eb = ex2_f16x2(pack_f16x2(s[nt][2], s[nt][3]));
                hadd2_acc(hl0, ea);
                hadd2_acc(hl1, eb);
                ap[nt >> 1][(nt & 1) * 2 + 0] = ea;
                ap[nt >> 1][(nt & 1) * 2 + 1] = eb;
            }
            l0 += hsum2_f32(hl0);
            l1 += hsum2_f32(hl1);
        }
        // PV ks=0,1 (issued now)
        #pragma unroll
        for (int ks = 0; ks < 2; ks++) {
            const uint32_t vbase = sVb[buf] + (uint32_t)ks * 2048u;
            #pragma unroll
            for (int nt2 = 0; nt2 < 4; nt2++) {
                uint32_t v0, v1, v2, v3;
                ldsm4t(vbase + inner[nt2], v0, v1, v2, v3);
                mma16816(o[2*nt2],   ap[ks], v0, v1);
                mma16816(o[2*nt2+1], ap[ks], v2, v3);
            }
        }
        // exp second half (overlaps PV ks=0,1 drain) -> writes ap[2], ap[3]
        {
            uint32_t hl0 = 0u, hl1 = 0u;
            #pragma unroll
            for (int nt = 4; nt < 8; nt++) {
                uint32_t ea = ex2_f16x2(pack_f16x2(s[nt][0], s[nt][1]));
                uint32_t eb = ex2_f16x2(pack_f16x2(s[nt][2], s[nt][3]));
                hadd2_acc(hl0, ea);
                hadd2_acc(hl1, eb);
                ap[nt >> 1][(nt & 1) * 2 + 0] = ea;
                ap[nt >> 1][(nt & 1) * 2 + 1] = eb;
            }
            l0 += hsum2_f32(hl0);
            l1 += hsum2_f32(hl1);
        }
        // PV ks=2,3: load fragments only; MMAs deferred past the next sync
        {
            const uint32_t vb2 = sVb[buf] + (uint32_t)2 * 2048u;
            const uint32_t vb3 = sVb[buf] + (uint32_t)3 * 2048u;
            #pragma unroll
            for (int nt2 = 0; nt2 < 4; nt2++)
                ldsm4t(vb2 + inner[nt2], vdef[4*nt2+0], vdef[4*nt2+1],
                       vdef[4*nt2+2], vdef[4*nt2+3]);
            #pragma unroll
            for (int nt2 = 0; nt2 < 4; nt2++)
                ldsm4t(vb3 + inner[nt2], vdef[16+4*nt2+0], vdef[16+4*nt2+1],
                       vdef[16+4*nt2+2], vdef[16+4*nt2+3]);
        }
        // no trailing sync — next iteration's leading sync provides it
    }

    // flush deferred PV ks=2,3 of tile 63
    #pragma unroll
    for (int nt2 = 0; nt2 < 4; nt2++) {
        mma16816(o[2*nt2],   ap[2], vdef[4*nt2+0], vdef[4*nt2+1]);
        mma16816(o[2*nt2+1], ap[2], vdef[4*nt2+2], vdef[4*nt2+3]);
    }
    #pragma unroll
    for (int nt2 = 0; nt2 < 4; nt2++) {
        mma16816(o[2*nt2],   ap[3], vdef[16+4*nt2+0], vdef[16+4*nt2+1]);
        mma16816(o[2*nt2+1], ap[3], vdef[16+4*nt2+2], vdef[16+4*nt2+3]);
    }

    l0 += __shfl_xor_sync(0xffffffffu, l0, 1);
    l0 += __shfl_xor_sync(0xffffffffu, l0, 2);
    l1 += __shfl_xor_sync(0xffffffffu, l1, 1);
    l1 += __shfl_xor_sync(0xffffffffu, l1, 2);
    const float inv0 = 1.f / l0, inv1 = 1.f / l1;

    const int b = bh >> 3, h = bh & 7;
    const int r0g = qblk * 64 + wid * 16 + (lane >> 2);
    const int cb = (lane & 3) * 2;
    #pragma unroll
    for (int nt = 0; nt < 8; nt++) {
        int col = h * DHH + nt * 8 + cb;
        *(uint32_t*)(g_attnh + (size_t)(b * NN + r0g) * DD + col) =
            pack_f16x2(o[nt][0] * inv0, o[nt][1] * inv0);
        *(uint32_t*)(g_attnh + (size_t)(b * NN + r0g + 8) * DD + col) =
            pack_f16x2(o[nt][2] * inv1, o[nt][3] * inv1);
    }
}

extern "C" void kernel_launch(void* const* d_in, const int* in_sizes, int n_in,
                              void* d_out, int out_size)
{
    const float* x  = (const float*)d_in[0];
    const float* Wq = (const float*)d_in[1];
    const float* Wk = (const float*)d_in[2];
    const float* Wv = (const float*)d_in[3];
    const float* Wo = (const float*)d_in[4];
    const float* bo = (const float*)d_in[5];
    float* out = (float*)d_out;

    cudaFuncSetAttribute(qkv_hmma_kernel,
                         cudaFuncAttributeMaxDynamicSharedMemorySize, 98304);
    cudaFuncSetAttribute(proj_hmma_kernel,
                         cudaFuncAttributeMaxDynamicSharedMemorySize, 98304);

    cvt_all_kernel<<<5120, 256>>>(x, Wq, Wk, Wv, Wo);
    qkv_hmma_kernel<<<dim3(64, 4, 3), 256, 98304>>>();
    attn_mma_kernel<<<dim3(64, 16), 128>>>();
    proj_hmma_kernel<<<dim3(64, 4), 256, 98304>>>(bo, out);
}